// round 4
// baseline (speedup 1.0000x reference)
#include <cuda_runtime.h>
#include <math.h>

// ---------------- problem constants ----------------
#define BB      2
#define SS      2048
#define DIMD    2048
#define NHH     16
#define QLORA   1536
#define KVLORA  512
#define ROPED   64
#define NOPED   128
#define VHDD    128
#define QKHD    192            // NOPED + ROPED
#define KVAW    576            // KVLORA + ROPED
#define ROWS    (BB*SS)        // 4096
#define SCALE_V 0.07216878364870323f   // 192^-0.5

// ---------------- scratch (device globals; no allocation allowed) -------
__device__ float g_qa [ROWS * QLORA];          // x @ wq_a^T (+rmsnorm in place)
__device__ float g_q  [ROWS * (NHH*QKHD)];     // q after wq_b (+rope in place)
__device__ float g_kva[ROWS * KVAW];           // x @ wkv_a^T (+norm/rope in place)
__device__ float g_kv [ROWS * (NHH*(NOPED+VHDD))]; // kv after wkv_b
__device__ float g_ao [ROWS * (NHH*VHDD)];     // attention output

// ============================================================================
// SGEMM: C[M,N] = A[M,K] @ W[N,K]^T + bias[N]
// 128x128 block tile, BK=8, 256 threads, 8x8 micro-tile per thread.
// A given with row stride lda; W row-major [N,K]; C row-major [M,N].
// M must be a multiple of 128; K a multiple of 8; N a multiple of 4.
// ============================================================================
__global__ __launch_bounds__(256, 2) void sgemm_bias(
    const float* __restrict__ A, int lda,
    const float* __restrict__ W,
    const float* __restrict__ bias,
    float* __restrict__ C,
    int N, int K)
{
    __shared__ float As[8][128];
    __shared__ float Bs[8][128];

    const int tid = threadIdx.x;
    const int tx = tid & 15;
    const int ty = tid >> 4;
    const int bm = blockIdx.y * 128;
    const int bn = blockIdx.x * 128;

    // loader mapping: 2 threads per row, each loads a float4 of K
    const int lr = tid >> 1;          // 0..127
    const int lc = (tid & 1) * 4;     // 0 or 4
    const float* Ap = A + (size_t)(bm + lr) * lda + lc;
    const float* Wp = W + (size_t)(bn + lr) * K + lc;
    const bool   wv = (bn + lr) < N;

    float acc[8][8];
#pragma unroll
    for (int i = 0; i < 8; i++)
#pragma unroll
        for (int j = 0; j < 8; j++) acc[i][j] = 0.f;

    for (int k0 = 0; k0 < K; k0 += 8) {
        float4 av = *(const float4*)(Ap + k0);
        float4 wvv = wv ? *(const float4*)(Wp + k0) : make_float4(0.f, 0.f, 0.f, 0.f);
        __syncthreads();
        As[lc + 0][lr] = av.x;  As[lc + 1][lr] = av.y;
        As[lc + 2][lr] = av.z;  As[lc + 3][lr] = av.w;
        Bs[lc + 0][lr] = wvv.x; Bs[lc + 1][lr] = wvv.y;
        Bs[lc + 2][lr] = wvv.z; Bs[lc + 3][lr] = wvv.w;
        __syncthreads();
#pragma unroll
        for (int kk = 0; kk < 8; kk++) {
            float4 a0 = *(const float4*)&As[kk][ty * 4];
            float4 a1 = *(const float4*)&As[kk][ty * 4 + 64];
            float4 b0 = *(const float4*)&Bs[kk][tx * 4];
            float4 b1 = *(const float4*)&Bs[kk][tx * 4 + 64];
            float ar[8] = {a0.x, a0.y, a0.z, a0.w, a1.x, a1.y, a1.z, a1.w};
            float br[8] = {b0.x, b0.y, b0.z, b0.w, b1.x, b1.y, b1.z, b1.w};
#pragma unroll
            for (int i = 0; i < 8; i++)
#pragma unroll
                for (int j = 0; j < 8; j++)
                    acc[i][j] = fmaf(ar[i], br[j], acc[i][j]);
        }
    }

    // epilogue with bias
    const int c0 = bn + tx * 4;
    const int c1 = bn + 64 + tx * 4;
    float4 bv0 = make_float4(0.f,0.f,0.f,0.f), bv1 = make_float4(0.f,0.f,0.f,0.f);
    if (c0 < N) bv0 = *(const float4*)(bias + c0);
    if (c1 < N) bv1 = *(const float4*)(bias + c1);
#pragma unroll
    for (int i = 0; i < 8; i++) {
        int r = bm + ((i < 4) ? (ty * 4 + i) : (64 + ty * 4 + (i - 4)));
        float* crow = C + (size_t)r * N;
        if (c0 < N) {
            float4 o = make_float4(acc[i][0] + bv0.x, acc[i][1] + bv0.y,
                                   acc[i][2] + bv0.z, acc[i][3] + bv0.w);
            *(float4*)(crow + c0) = o;
        }
        if (c1 < N) {
            float4 o = make_float4(acc[i][4] + bv1.x, acc[i][5] + bv1.y,
                                   acc[i][6] + bv1.z, acc[i][7] + bv1.w);
            *(float4*)(crow + c1) = o;
        }
    }
}

// ============================================================================
// RMSNorm (in place): row of length `stride`, normalize first `n` elements.
// One block (256 threads) per row. n multiple of 4.
// ============================================================================
__global__ __launch_bounds__(256) void rmsnorm_k(
    float* __restrict__ x, const float* __restrict__ w, int stride, int n)
{
    float* row = x + (size_t)blockIdx.x * stride;
    float ss = 0.f;
    for (int i = threadIdx.x * 4; i < n; i += 256 * 4) {
        float4 v = *(const float4*)(row + i);
        ss += v.x * v.x + v.y * v.y + v.z * v.z + v.w * v.w;
    }
#pragma unroll
    for (int off = 16; off; off >>= 1)
        ss += __shfl_xor_sync(0xffffffffu, ss, off);
    __shared__ float ws[8];
    if ((threadIdx.x & 31) == 0) ws[threadIdx.x >> 5] = ss;
    __syncthreads();
    float tot = 0.f;
#pragma unroll
    for (int i = 0; i < 8; i++) tot += ws[i];
    float r = rsqrtf(tot / (float)n + 1e-6f);
    for (int i = threadIdx.x * 4; i < n; i += 256 * 4) {
        float4 v  = *(const float4*)(row + i);
        float4 wv = *(const float4*)(w + i);
        v.x *= r * wv.x;  v.y *= r * wv.y;
        v.z *= r * wv.z;  v.w *= r * wv.w;
        *(float4*)(row + i) = v;
    }
}

// ============================================================================
// RoPE on q (in place): q is (B,S,NH,192), rope on dims [128..191].
// ============================================================================
__global__ void rope_q_k(float* __restrict__ q,
                         const float* __restrict__ cosd,
                         const float* __restrict__ sind)
{
    int idx = blockIdx.x * blockDim.x + threadIdx.x;  // B*S*NH*32 total
    int i = idx & 31;
    int h = (idx >> 5) & 15;
    int s = (idx >> 9) & 2047;
    int b = idx >> 20;
    float* p = q + ((size_t)((b * SS + s)) * NHH + h) * QKHD + NOPED + 2 * i;
    float c  = cosd[s * 32 + i];
    float sn = sind[s * 32 + i];
    float xr = p[0], xi = p[1];
    p[0] = xr * c - xi * sn;
    p[1] = xr * sn + xi * c;
}

// RoPE on k_pe (in place): kva is (B,S,576), rope on dims [512..575].
__global__ void rope_kpe_k(float* __restrict__ kva,
                           const float* __restrict__ cosd,
                           const float* __restrict__ sind)
{
    int idx = blockIdx.x * blockDim.x + threadIdx.x;  // B*S*32 total
    int i = idx & 31;
    int s = (idx >> 5) & 2047;
    int b = idx >> 16;
    float* p = kva + (size_t)(b * SS + s) * KVAW + KVLORA + 2 * i;
    float c  = cosd[s * 32 + i];
    float sn = sind[s * 32 + i];
    float xr = p[0], xi = p[1];
    p[0] = xr * c - xi * sn;
    p[1] = xr * sn + xi * c;
}

// ============================================================================
// Flash attention (causal). One block per (q-tile of 64, head, batch).
// Q: (B,S,NH,192); KV: (B,S,NH,256) [0:128]=k_nope, [128:256]=v;
// KPE: (B,S,576) roped k_pe at [512:576] (shared across heads).
// Smem: Qs[192][64], Ks[192][64] (d-major, transposed), Vs[64][132], Ps[64][64].
// ============================================================================
#define FLASH_SMEM ((192*64 + 192*64 + 64*132 + 64*64) * sizeof(float))

__global__ __launch_bounds__(256, 1) void flash_attn(
    const float* __restrict__ Q, const float* __restrict__ KV,
    const float* __restrict__ KPE, float* __restrict__ Oo)
{
    extern __shared__ float sm[];
    float* Qs = sm;                   // [192][64]
    float* Ks = Qs + 192 * 64;        // [192][64]
    float* Vs = Ks + 192 * 64;        // [64][132] (padded stride)
    float* Ps = Vs + 64 * 132;        // [64][64]

    const int tid = threadIdx.x;
    const int tx = tid & 15;
    const int ty = tid >> 4;
    const int qt = (int)(gridDim.x - 1) - (int)blockIdx.x;  // big tiles first
    const int h  = blockIdx.y;
    const int b  = blockIdx.z;
    const int q0 = qt * 64;

    // ---- load Q transposed (d-major), conflict-free STS: 32 distinct rows/warp
    {
        const int r  = tid & 63;
        const int cb = tid >> 6;
        const float* qrow = Q + ((size_t)(b * SS + q0 + r) * NHH + h) * QKHD;
#pragma unroll
        for (int it = 0; it < 12; ++it) {
            int d0 = (cb + it * 4) * 4;
            float4 v = *(const float4*)(qrow + d0);
            Qs[(d0 + 0) * 64 + r] = v.x;
            Qs[(d0 + 1) * 64 + r] = v.y;
            Qs[(d0 + 2) * 64 + r] = v.z;
            Qs[(d0 + 3) * 64 + r] = v.w;
        }
    }

    float o[4][8];
#pragma unroll
    for (int i = 0; i < 4; i++)
#pragma unroll
        for (int j = 0; j < 8; j++) o[i][j] = 0.f;
    float mold[4] = {-1e30f, -1e30f, -1e30f, -1e30f};
    float lsum[4] = {0.f, 0.f, 0.f, 0.f};

    for (int kt = 0; kt <= qt; ++kt) {
        const int k0 = kt * 64;
        // ---- load K (transposed, nope from KV + pe from KPE) and V
        {
            const int r  = tid & 63;
            const int cb = tid >> 6;
            const float* kvrow  = KV  + ((size_t)(b * SS + k0 + r) * NHH + h) * (NOPED + VHDD);
            const float* kperow = KPE + (size_t)(b * SS + k0 + r) * KVAW + KVLORA;
#pragma unroll
            for (int it = 0; it < 12; ++it) {
                int d0 = (cb + it * 4) * 4;
                float4 v = (d0 < NOPED) ? *(const float4*)(kvrow + d0)
                                        : *(const float4*)(kperow + (d0 - NOPED));
                Ks[(d0 + 0) * 64 + r] = v.x;
                Ks[(d0 + 1) * 64 + r] = v.y;
                Ks[(d0 + 2) * 64 + r] = v.z;
                Ks[(d0 + 3) * 64 + r] = v.w;
            }
            const int vk  = tid >> 2;
            const int vc4 = tid & 3;
            const float* vrow = KV + ((size_t)(b * SS + k0 + vk) * NHH + h) * (NOPED + VHDD) + NOPED;
#pragma unroll
            for (int it = 0; it < 8; ++it) {
                int c0 = (vc4 + it * 4) * 4;
                *(float4*)&Vs[vk * 132 + c0] = *(const float4*)(vrow + c0);
            }
        }
        __syncthreads();

        // ---- scores: S[64x64] = Q . K^T over d=192; thread owns 4x4
        float acc[4][4];
#pragma unroll
        for (int i = 0; i < 4; i++)
#pragma unroll
            for (int j = 0; j < 4; j++) acc[i][j] = 0.f;
#pragma unroll 8
        for (int d = 0; d < 192; ++d) {
            float4 qa = *(const float4*)(Qs + d * 64 + (ty << 2));
            float4 ka = *(const float4*)(Ks + d * 64 + (tx << 2));
            acc[0][0] = fmaf(qa.x, ka.x, acc[0][0]);
            acc[0][1] = fmaf(qa.x, ka.y, acc[0][1]);
            acc[0][2] = fmaf(qa.x, ka.z, acc[0][2]);
            acc[0][3] = fmaf(qa.x, ka.w, acc[0][3]);
            acc[1][0] = fmaf(qa.y, ka.x, acc[1][0]);
            acc[1][1] = fmaf(qa.y, ka.y, acc[1][1]);
            acc[1][2] = fmaf(qa.y, ka.z, acc[1][2]);
            acc[1][3] = fmaf(qa.y, ka.w, acc[1][3]);
            acc[2][0] = fmaf(qa.z, ka.x, acc[2][0]);
            acc[2][1] = fmaf(qa.z, ka.y, acc[2][1]);
            acc[2][2] = fmaf(qa.z, ka.z, acc[2][2]);
            acc[2][3] = fmaf(qa.z, ka.w, acc[2][3]);
            acc[3][0] = fmaf(qa.w, ka.x, acc[3][0]);
            acc[3][1] = fmaf(qa.w, ka.y, acc[3][1]);
            acc[3][2] = fmaf(qa.w, ka.z, acc[3][2]);
            acc[3][3] = fmaf(qa.w, ka.w, acc[3][3]);
        }

        // ---- online softmax (row = ty*4+i; reduce over 16-lane half-warp)
        const bool diag = (kt == qt);
#pragma unroll
        for (int i = 0; i < 4; i++) {
            const int lrow = (ty << 2) + i;
            float s0 = acc[i][0] * SCALE_V;
            float s1 = acc[i][1] * SCALE_V;
            float s2 = acc[i][2] * SCALE_V;
            float s3 = acc[i][3] * SCALE_V;
            if (diag) {
                int c = tx << 2;
                if (c + 0 > lrow) s0 = -1e30f;
                if (c + 1 > lrow) s1 = -1e30f;
                if (c + 2 > lrow) s2 = -1e30f;
                if (c + 3 > lrow) s3 = -1e30f;
            }
            float mx = fmaxf(fmaxf(s0, s1), fmaxf(s2, s3));
            mx = fmaxf(mx, __shfl_xor_sync(0xffffffffu, mx, 8));
            mx = fmaxf(mx, __shfl_xor_sync(0xffffffffu, mx, 4));
            mx = fmaxf(mx, __shfl_xor_sync(0xffffffffu, mx, 2));
            mx = fmaxf(mx, __shfl_xor_sync(0xffffffffu, mx, 1));
            float mnew = fmaxf(mold[i], mx);
            float fac  = __expf(mold[i] - mnew);
            mold[i] = mnew;
            float p0 = __expf(s0 - mnew);
            float p1 = __expf(s1 - mnew);
            float p2 = __expf(s2 - mnew);
            float p3 = __expf(s3 - mnew);
            float ssum = p0 + p1 + p2 + p3;
            ssum += __shfl_xor_sync(0xffffffffu, ssum, 8);
            ssum += __shfl_xor_sync(0xffffffffu, ssum, 4);
            ssum += __shfl_xor_sync(0xffffffffu, ssum, 2);
            ssum += __shfl_xor_sync(0xffffffffu, ssum, 1);
            lsum[i] = lsum[i] * fac + ssum;
#pragma unroll
            for (int j = 0; j < 8; j++) o[i][j] *= fac;
            *(float4*)(Ps + lrow * 64 + (tx << 2)) = make_float4(p0, p1, p2, p3);
        }
        __syncthreads();

        // ---- PV: O[64x128] += P[64x64] . V[64x128]; thread owns 4 rows x 8 cols
#pragma unroll 4
        for (int k = 0; k < 64; ++k) {
            float p0 = Ps[((ty << 2) + 0) * 64 + k];
            float p1 = Ps[((ty << 2) + 1) * 64 + k];
            float p2 = Ps[((ty << 2) + 2) * 64 + k];
            float p3 = Ps[((ty << 2) + 3) * 64 + k];
            float4 va = *(const float4*)(Vs + k * 132 + (tx << 3));
            float4 vb = *(const float4*)(Vs + k * 132 + (tx << 3) + 4);
            o[0][0] = fmaf(p0, va.x, o[0][0]); o[0][1] = fmaf(p0, va.y, o[0][1]);
            o[0][2] = fmaf(p0, va.z, o[0][2]); o[0][3] = fmaf(p0, va.w, o[0][3]);
            o[0][4] = fmaf(p0, vb.x, o[0][4]); o[0][5] = fmaf(p0, vb.y, o[0][5]);
            o[0][6] = fmaf(p0, vb.z, o[0][6]); o[0][7] = fmaf(p0, vb.w, o[0][7]);
            o[1][0] = fmaf(p1, va.x, o[1][0]); o[1][1] = fmaf(p1, va.y, o[1][1]);
            o[1][2] = fmaf(p1, va.z, o[1][2]); o[1][3] = fmaf(p1, va.w, o[1][3]);
            o[1][4] = fmaf(p1, vb.x, o[1][4]); o[1][5] = fmaf(p1, vb.y, o[1][5]);
            o[1][6] = fmaf(p1, vb.z, o[1][6]); o[1][7] = fmaf(p1, vb.w, o[1][7]);
            o[2][0] = fmaf(p2, va.x, o[2][0]); o[2][1] = fmaf(p2, va.y, o[2][1]);
            o[2][2] = fmaf(p2, va.z, o[2][2]); o[2][3] = fmaf(p2, va.w, o[2][3]);
            o[2][4] = fmaf(p2, vb.x, o[2][4]); o[2][5] = fmaf(p2, vb.y, o[2][5]);
            o[2][6] = fmaf(p2, vb.z, o[2][6]); o[2][7] = fmaf(p2, vb.w, o[2][7]);
            o[3][0] = fmaf(p3, va.x, o[3][0]); o[3][1] = fmaf(p3, va.y, o[3][1]);
            o[3][2] = fmaf(p3, va.z, o[3][2]); o[3][3] = fmaf(p3, va.w, o[3][3]);
            o[3][4] = fmaf(p3, vb.x, o[3][4]); o[3][5] = fmaf(p3, vb.y, o[3][5]);
            o[3][6] = fmaf(p3, vb.z, o[3][6]); o[3][7] = fmaf(p3, vb.w, o[3][7]);
        }
        __syncthreads();
    }

    // ---- write O / l
#pragma unroll
    for (int i = 0; i < 4; i++) {
        float inv = 1.0f / lsum[i];
        float* orow = Oo + ((size_t)(b * SS + q0 + (ty << 2) + i) * NHH + h) * VHDD + (tx << 3);
        *(float4*)orow       = make_float4(o[i][0] * inv, o[i][1] * inv, o[i][2] * inv, o[i][3] * inv);
        *(float4*)(orow + 4) = make_float4(o[i][4] * inv, o[i][5] * inv, o[i][6] * inv, o[i][7] * inv);
    }
}

// ============================================================================
// launch
// ============================================================================
extern "C" void kernel_launch(void* const* d_in, const int* in_sizes, int n_in,
                              void* d_out, int out_size)
{
    const float* x         = (const float*)d_in[0];
    const float* fcos      = (const float*)d_in[1];
    const float* fsin      = (const float*)d_in[2];
    const float* wq_a_w    = (const float*)d_in[3];
    const float* wq_a_b    = (const float*)d_in[4];
    const float* q_norm_w  = (const float*)d_in[5];
    const float* wq_b_w    = (const float*)d_in[6];
    const float* wq_b_b    = (const float*)d_in[7];
    const float* wkv_a_w   = (const float*)d_in[8];
    const float* wkv_a_b   = (const float*)d_in[9];
    const float* kv_norm_w = (const float*)d_in[10];
    const float* wkv_b_w   = (const float*)d_in[11];
    const float* wkv_b_b   = (const float*)d_in[12];
    const float* wo_w      = (const float*)d_in[13];
    const float* wo_b      = (const float*)d_in[14];
    float* out = (float*)d_out;

    float *qa, *q, *kva, *kv, *ao;
    cudaGetSymbolAddress((void**)&qa,  g_qa);
    cudaGetSymbolAddress((void**)&q,   g_q);
    cudaGetSymbolAddress((void**)&kva, g_kva);
    cudaGetSymbolAddress((void**)&kv,  g_kv);
    cudaGetSymbolAddress((void**)&ao,  g_ao);

    // 1) qa = x @ wq_a^T + b         (4096 x 1536, K=2048)
    sgemm_bias<<<dim3(QLORA / 128, ROWS / 128), 256>>>(x, DIMD, wq_a_w, wq_a_b, qa, QLORA, DIMD);
    // 2) kva = x @ wkv_a^T + b       (4096 x 576, K=2048)
    sgemm_bias<<<dim3((KVAW + 127) / 128, ROWS / 128), 256>>>(x, DIMD, wkv_a_w, wkv_a_b, kva, KVAW, DIMD);
    // 3) rmsnorm(qa) over 1536
    rmsnorm_k<<<ROWS, 256>>>(qa, q_norm_w, QLORA, QLORA);
    // 4) rmsnorm(kv_c) over first 512 of each 576-row
    rmsnorm_k<<<ROWS, 256>>>(kva, kv_norm_w, KVAW, KVLORA);
    // 5) rope on k_pe (cols 512..575)
    rope_kpe_k<<<(BB * SS * 32) / 256, 256>>>(kva, fcos, fsin);
    // 6) q = qa @ wq_b^T + b         (4096 x 3072, K=1536)
    sgemm_bias<<<dim3((NHH * QKHD) / 128, ROWS / 128), 256>>>(qa, QLORA, wq_b_w, wq_b_b, q, NHH * QKHD, QLORA);
    // 7) rope on q_pe
    rope_q_k<<<(BB * SS * NHH * 32) / 256, 256>>>(q, fcos, fsin);
    // 8) kv = rmsnorm(kv_c) @ wkv_b^T + b   (4096 x 4096, K=512, lda=576)
    sgemm_bias<<<dim3((NHH * (NOPED + VHDD)) / 128, ROWS / 128), 256>>>(kva, KVAW, wkv_b_w, wkv_b_b, kv, NHH * (NOPED + VHDD), KVLORA);
    // 9) causal flash attention -> ao
    cudaFuncSetAttribute(flash_attn, cudaFuncAttributeMaxDynamicSharedMemorySize, (int)FLASH_SMEM);
    flash_attn<<<dim3(SS / 64, NHH, BB), 256, FLASH_SMEM>>>(q, kv, kva, ao);
    // 10) out = ao @ wo^T + b        (4096 x 2048, K=2048)
    sgemm_bias<<<dim3(DIMD / 128, ROWS / 128), 256>>>(ao, NHH * VHDD, wo_w, wo_b, out, DIMD, DIMD);
}

// round 6
// speedup vs baseline: 1.4301x; 1.4301x over previous
#include <cuda_runtime.h>
#include <cuda_bf16.h>
#include <cstdint>
#include <math.h>

// ---------------- problem constants ----------------
#define BB      2
#define SS      2048
#define DIMD    2048
#define NHH     16
#define QLORA   1536
#define KVLORA  512
#define ROPED   64
#define NOPED   128
#define VHDD    128
#define QKHD    192            // NOPED + ROPED
#define KVAW    576            // KVLORA + ROPED
#define ROWS    (BB*SS)        // 4096
#define SCALE_V 0.07216878364870323f   // 192^-0.5

// ---------------- scratch (device globals; no allocation allowed) -------
__device__ float g_qa [ROWS * QLORA];
__device__ float g_q  [ROWS * (NHH*QKHD)];
__device__ float g_kva[ROWS * KVAW];
__device__ float g_kv [ROWS * (NHH*(NOPED+VHDD))];
__device__ float g_ao [ROWS * (NHH*VHDD)];

// ============================================================================
// bf16 split helpers
// ============================================================================
__device__ __forceinline__ uint32_t pack_bf(float a, float b) {
    uint16_t lo16 = __bfloat16_as_ushort(__float2bfloat16_rn(a));
    uint16_t hi16 = __bfloat16_as_ushort(__float2bfloat16_rn(b));
    return (uint32_t)lo16 | ((uint32_t)hi16 << 16);
}
__device__ __forceinline__ void cvt_split4(float4 v, uint2& hi, uint2& lo) {
    float hx = __bfloat162float(__float2bfloat16_rn(v.x));
    float hy = __bfloat162float(__float2bfloat16_rn(v.y));
    float hz = __bfloat162float(__float2bfloat16_rn(v.z));
    float hw = __bfloat162float(__float2bfloat16_rn(v.w));
    hi.x = pack_bf(v.x, v.y);
    hi.y = pack_bf(v.z, v.w);
    lo.x = pack_bf(v.x - hx, v.y - hy);
    lo.y = pack_bf(v.z - hz, v.w - hw);
}

// mma.sync m16n8k16 row.col f32.bf16.bf16.f32  (HMMA, portable PTX)
__device__ __forceinline__ void mma16816(float* d, const uint32_t* a, const uint32_t* b) {
    asm volatile(
        "mma.sync.aligned.m16n8k16.row.col.f32.bf16.bf16.f32 "
        "{%0,%1,%2,%3}, {%4,%5,%6,%7}, {%8,%9}, {%0,%1,%2,%3};"
        : "+f"(d[0]), "+f"(d[1]), "+f"(d[2]), "+f"(d[3])
        : "r"(a[0]), "r"(a[1]), "r"(a[2]), "r"(a[3]), "r"(b[0]), "r"(b[1]));
}

// ============================================================================
// Tensor-core GEMM: C[M,N] = A[M,K] @ W[N,K]^T + bias[N]
// fp32 in/out via split-bf16 3-pass (AhBh + AhBl + AlBh) in fp32 accumulators.
// CTA 128x128, 256 thr (8 warps, 2x4), K-chunk 32, double-buffered smem.
// smem tiles: 128 rows x 32 bf16, row stride 20 words (40 bf16) -> frag LDS
// conflict-free. Stage = Ahi|Alo|Bhi|Blo = 4*10240B; 2 stages = 80KB.
// Requires: M % 128 == 0, K % 32 == 0, N even.
// ============================================================================
#define ASZW   2560                    // words per tile (128*20)
#define STAGEW (4*ASZW)                // words per stage
#define GEMM_SMEM (2*STAGEW*4)         // bytes

__global__ __launch_bounds__(256, 1) void sgemm_hmma(
    const float* __restrict__ A, int lda,
    const float* __restrict__ W,
    const float* __restrict__ bias,
    float* __restrict__ C, int N, int K)
{
    extern __shared__ uint32_t smw[];
    const int tid  = threadIdx.x;
    const int lane = tid & 31;
    const int wid  = tid >> 5;
    const int warp_m = wid & 1;        // 0..1 -> 64-row slab
    const int warp_n = wid >> 1;       // 0..3 -> 32-col slab
    const int bm = blockIdx.y * 128;
    const int bn = blockIdx.x * 128;
    const int t = lane & 3;
    const int g = lane >> 2;

    float acc[4][4][4];
#pragma unroll
    for (int i = 0; i < 4; i++)
#pragma unroll
        for (int j = 0; j < 4; j++)
#pragma unroll
            for (int k = 0; k < 4; k++) acc[i][j][k] = 0.f;

    float4 pa[4], pb[4];
    const int nc = K >> 5;

    // ---- prologue: load chunk 0
#pragma unroll
    for (int i = 0; i < 4; ++i) {
        int f = tid + i * 256;
        int row = f >> 3, colf = f & 7;
        pa[i] = *(const float4*)(A + (size_t)(bm + row) * lda + colf * 4);
        pb[i] = (bn + row < N) ? *(const float4*)(W + (size_t)(bn + row) * K + colf * 4)
                               : make_float4(0.f, 0.f, 0.f, 0.f);
    }
    {
        uint32_t* st = smw;            // stage 0
#pragma unroll
        for (int i = 0; i < 4; ++i) {
            int f = tid + i * 256;
            int row = f >> 3, colf = f & 7;
            int widx = row * 20 + colf * 2;
            uint2 hi, lo;
            cvt_split4(pa[i], hi, lo);
            *(uint2*)(st + widx)            = hi;
            *(uint2*)(st + ASZW + widx)     = lo;
            cvt_split4(pb[i], hi, lo);
            *(uint2*)(st + 2 * ASZW + widx) = hi;
            *(uint2*)(st + 3 * ASZW + widx) = lo;
        }
    }
    __syncthreads();

    for (int ck = 0; ck < nc; ++ck) {
        // prefetch next chunk to regs
        if (ck + 1 < nc) {
            const int k0 = (ck + 1) << 5;
#pragma unroll
            for (int i = 0; i < 4; ++i) {
                int f = tid + i * 256;
                int row = f >> 3, colf = f & 7;
                pa[i] = *(const float4*)(A + (size_t)(bm + row) * lda + k0 + colf * 4);
                pb[i] = (bn + row < N) ? *(const float4*)(W + (size_t)(bn + row) * K + k0 + colf * 4)
                                       : make_float4(0.f, 0.f, 0.f, 0.f);
            }
        }

        // ---- compute current stage
        {
            uint32_t* Ah = smw + (ck & 1) * STAGEW;
            uint32_t* Al = Ah + ASZW;
            uint32_t* Bh = Ah + 2 * ASZW;
            uint32_t* Bl = Ah + 3 * ASZW;
#pragma unroll
            for (int k16 = 0; k16 < 2; ++k16) {
                const int kp = k16 * 8;
                uint32_t bh[4][2], bl[4][2];
#pragma unroll
                for (int nt = 0; nt < 4; ++nt) {
                    int idx = (warp_n * 32 + nt * 8 + g) * 20 + kp + t;
                    bh[nt][0] = Bh[idx];     bh[nt][1] = Bh[idx + 4];
                    bl[nt][0] = Bl[idx];     bl[nt][1] = Bl[idx + 4];
                }
#pragma unroll
                for (int mt = 0; mt < 4; ++mt) {
                    int base = (warp_m * 64 + mt * 16 + g) * 20 + kp + t;
                    uint32_t ah[4], al[4];
                    ah[0] = Ah[base];       ah[1] = Ah[base + 160];
                    ah[2] = Ah[base + 4];   ah[3] = Ah[base + 164];
                    al[0] = Al[base];       al[1] = Al[base + 160];
                    al[2] = Al[base + 4];   al[3] = Al[base + 164];
#pragma unroll
                    for (int nt = 0; nt < 4; ++nt) {
                        mma16816(acc[mt][nt], ah, bh[nt]);
                        mma16816(acc[mt][nt], ah, bl[nt]);
                        mma16816(acc[mt][nt], al, bh[nt]);
                    }
                }
            }
        }

        // ---- convert + STS next chunk into the other stage
        if (ck + 1 < nc) {
            uint32_t* st = smw + ((ck + 1) & 1) * STAGEW;
#pragma unroll
            for (int i = 0; i < 4; ++i) {
                int f = tid + i * 256;
                int row = f >> 3, colf = f & 7;
                int widx = row * 20 + colf * 2;
                uint2 hi, lo;
                cvt_split4(pa[i], hi, lo);
                *(uint2*)(st + widx)            = hi;
                *(uint2*)(st + ASZW + widx)     = lo;
                cvt_split4(pb[i], hi, lo);
                *(uint2*)(st + 2 * ASZW + widx) = hi;
                *(uint2*)(st + 3 * ASZW + widx) = lo;
            }
        }
        __syncthreads();
    }

    // ---- epilogue with bias
#pragma unroll
    for (int mt = 0; mt < 4; ++mt) {
        int r0 = bm + warp_m * 64 + mt * 16 + g;
#pragma unroll
        for (int nt = 0; nt < 4; ++nt) {
            int c = bn + warp_n * 32 + nt * 8 + t * 2;
            if (c < N) {
                float2 bv = *(const float2*)(bias + c);
                float2 o0 = make_float2(acc[mt][nt][0] + bv.x, acc[mt][nt][1] + bv.y);
                float2 o1 = make_float2(acc[mt][nt][2] + bv.x, acc[mt][nt][3] + bv.y);
                *(float2*)(C + (size_t)r0 * N + c)       = o0;
                *(float2*)(C + (size_t)(r0 + 8) * N + c) = o1;
            }
        }
    }
}

// ============================================================================
// RMSNorm (in place)
// ============================================================================
__global__ __launch_bounds__(256) void rmsnorm_k(
    float* __restrict__ x, const float* __restrict__ w, int stride, int n)
{
    float* row = x + (size_t)blockIdx.x * stride;
    float ss = 0.f;
    for (int i = threadIdx.x * 4; i < n; i += 256 * 4) {
        float4 v = *(const float4*)(row + i);
        ss += v.x * v.x + v.y * v.y + v.z * v.z + v.w * v.w;
    }
#pragma unroll
    for (int off = 16; off; off >>= 1)
        ss += __shfl_xor_sync(0xffffffffu, ss, off);
    __shared__ float ws[8];
    if ((threadIdx.x & 31) == 0) ws[threadIdx.x >> 5] = ss;
    __syncthreads();
    float tot = 0.f;
#pragma unroll
    for (int i = 0; i < 8; i++) tot += ws[i];
    float r = rsqrtf(tot / (float)n + 1e-6f);
    for (int i = threadIdx.x * 4; i < n; i += 256 * 4) {
        float4 v  = *(const float4*)(row + i);
        float4 wv = *(const float4*)(w + i);
        v.x *= r * wv.x;  v.y *= r * wv.y;
        v.z *= r * wv.z;  v.w *= r * wv.w;
        *(float4*)(row + i) = v;
    }
}

// ============================================================================
// RoPE kernels
// ============================================================================
__global__ void rope_q_k(float* __restrict__ q,
                         const float* __restrict__ cosd,
                         const float* __restrict__ sind)
{
    int idx = blockIdx.x * blockDim.x + threadIdx.x;
    int i = idx & 31;
    int h = (idx >> 5) & 15;
    int s = (idx >> 9) & 2047;
    int b = idx >> 20;
    float* p = q + ((size_t)((b * SS + s)) * NHH + h) * QKHD + NOPED + 2 * i;
    float c  = cosd[s * 32 + i];
    float sn = sind[s * 32 + i];
    float xr = p[0], xi = p[1];
    p[0] = xr * c - xi * sn;
    p[1] = xr * sn + xi * c;
}

__global__ void rope_kpe_k(float* __restrict__ kva,
                           const float* __restrict__ cosd,
                           const float* __restrict__ sind)
{
    int idx = blockIdx.x * blockDim.x + threadIdx.x;
    int i = idx & 31;
    int s = (idx >> 5) & 2047;
    int b = idx >> 16;
    float* p = kva + (size_t)(b * SS + s) * KVAW + KVLORA + 2 * i;
    float c  = cosd[s * 32 + i];
    float sn = sind[s * 32 + i];
    float xr = p[0], xi = p[1];
    p[0] = xr * c - xi * sn;
    p[1] = xr * sn + xi * c;
}

// ============================================================================
// Flash attention (causal), fp32 SIMT (unchanged from R4-passing version)
// ============================================================================
#define FLASH_SMEM ((192*64 + 192*64 + 64*132 + 64*64) * sizeof(float))

__global__ __launch_bounds__(256, 1) void flash_attn(
    const float* __restrict__ Q, const float* __restrict__ KV,
    const float* __restrict__ KPE, float* __restrict__ Oo)
{
    extern __shared__ float sm[];
    float* Qs = sm;
    float* Ks = Qs + 192 * 64;
    float* Vs = Ks + 192 * 64;
    float* Ps = Vs + 64 * 132;

    const int tid = threadIdx.x;
    const int tx = tid & 15;
    const int ty = tid >> 4;
    const int qt = (int)(gridDim.x - 1) - (int)blockIdx.x;
    const int h  = blockIdx.y;
    const int b  = blockIdx.z;
    const int q0 = qt * 64;

    {
        const int r  = tid & 63;
        const int cb = tid >> 6;
        const float* qrow = Q + ((size_t)(b * SS + q0 + r) * NHH + h) * QKHD;
#pragma unroll
        for (int it = 0; it < 12; ++it) {
            int d0 = (cb + it * 4) * 4;
            float4 v = *(const float4*)(qrow + d0);
            Qs[(d0 + 0) * 64 + r] = v.x;
            Qs[(d0 + 1) * 64 + r] = v.y;
            Qs[(d0 + 2) * 64 + r] = v.z;
            Qs[(d0 + 3) * 64 + r] = v.w;
        }
    }

    float o[4][8];
#pragma unroll
    for (int i = 0; i < 4; i++)
#pragma unroll
        for (int j = 0; j < 8; j++) o[i][j] = 0.f;
    float mold[4] = {-1e30f, -1e30f, -1e30f, -1e30f};
    float lsum[4] = {0.f, 0.f, 0.f, 0.f};

    for (int kt = 0; kt <= qt; ++kt) {
        const int k0 = kt * 64;
        {
            const int r  = tid & 63;
            const int cb = tid >> 6;
            const float* kvrow  = KV  + ((size_t)(b * SS + k0 + r) * NHH + h) * (NOPED + VHDD);
            const float* kperow = KPE + (size_t)(b * SS + k0 + r) * KVAW + KVLORA;
#pragma unroll
            for (int it = 0; it < 12; ++it) {
                int d0 = (cb + it * 4) * 4;
                float4 v = (d0 < NOPED) ? *(const float4*)(kvrow + d0)
                                        : *(const float4*)(kperow + (d0 - NOPED));
                Ks[(d0 + 0) * 64 + r] = v.x;
                Ks[(d0 + 1) * 64 + r] = v.y;
                Ks[(d0 + 2) * 64 + r] = v.z;
                Ks[(d0 + 3) * 64 + r] = v.w;
            }
            const int vk  = tid >> 2;
            const int vc4 = tid & 3;
            const float* vrow = KV + ((size_t)(b * SS + k0 + vk) * NHH + h) * (NOPED + VHDD) + NOPED;
#pragma unroll
            for (int it = 0; it < 8; ++it) {
                int c0 = (vc4 + it * 4) * 4;
                *(float4*)&Vs[vk * 132 + c0] = *(const float4*)(vrow + c0);
            }
        }
        __syncthreads();

        float acc[4][4];
#pragma unroll
        for (int i = 0; i < 4; i++)
#pragma unroll
            for (int j = 0; j < 4; j++) acc[i][j] = 0.f;
#pragma unroll 8
        for (int d = 0; d < 192; ++d) {
            float4 qa = *(const float4*)(Qs + d * 64 + (ty << 2));
            float4 ka = *(const float4*)(Ks + d * 64 + (tx << 2));
            acc[0][0] = fmaf(qa.x, ka.x, acc[0][0]);
            acc[0][1] = fmaf(qa.x, ka.y, acc[0][1]);
            acc[0][2] = fmaf(qa.x, ka.z, acc[0][2]);
            acc[0][3] = fmaf(qa.x, ka.w, acc[0][3]);
            acc[1][0] = fmaf(qa.y, ka.x, acc[1][0]);
            acc[1][1] = fmaf(qa.y, ka.y, acc[1][1]);
            acc[1][2] = fmaf(qa.y, ka.z, acc[1][2]);
            acc[1][3] = fmaf(qa.y, ka.w, acc[1][3]);
            acc[2][0] = fmaf(qa.z, ka.x, acc[2][0]);
            acc[2][1] = fmaf(qa.z, ka.y, acc[2][1]);
            acc[2][2] = fmaf(qa.z, ka.z, acc[2][2]);
            acc[2][3] = fmaf(qa.z, ka.w, acc[2][3]);
            acc[3][0] = fmaf(qa.w, ka.x, acc[3][0]);
            acc[3][1] = fmaf(qa.w, ka.y, acc[3][1]);
            acc[3][2] = fmaf(qa.w, ka.z, acc[3][2]);
            acc[3][3] = fmaf(qa.w, ka.w, acc[3][3]);
        }

        const bool diag = (kt == qt);
#pragma unroll
        for (int i = 0; i < 4; i++) {
            const int lrow = (ty << 2) + i;
            float s0 = acc[i][0] * SCALE_V;
            float s1 = acc[i][1] * SCALE_V;
            float s2 = acc[i][2] * SCALE_V;
            float s3 = acc[i][3] * SCALE_V;
            if (diag) {
                int c = tx << 2;
                if (c + 0 > lrow) s0 = -1e30f;
                if (c + 1 > lrow) s1 = -1e30f;
                if (c + 2 > lrow) s2 = -1e30f;
                if (c + 3 > lrow) s3 = -1e30f;
            }
            float mx = fmaxf(fmaxf(s0, s1), fmaxf(s2, s3));
            mx = fmaxf(mx, __shfl_xor_sync(0xffffffffu, mx, 8));
            mx = fmaxf(mx, __shfl_xor_sync(0xffffffffu, mx, 4));
            mx = fmaxf(mx, __shfl_xor_sync(0xffffffffu, mx, 2));
            mx = fmaxf(mx, __shfl_xor_sync(0xffffffffu, mx, 1));
            float mnew = fmaxf(mold[i], mx);
            float fac  = __expf(mold[i] - mnew);
            mold[i] = mnew;
            float p0 = __expf(s0 - mnew);
            float p1 = __expf(s1 - mnew);
            float p2 = __expf(s2 - mnew);
            float p3 = __expf(s3 - mnew);
            float ssum = p0 + p1 + p2 + p3;
            ssum += __shfl_xor_sync(0xffffffffu, ssum, 8);
            ssum += __shfl_xor_sync(0xffffffffu, ssum, 4);
            ssum += __shfl_xor_sync(0xffffffffu, ssum, 2);
            ssum += __shfl_xor_sync(0xffffffffu, ssum, 1);
            lsum[i] = lsum[i] * fac + ssum;
#pragma unroll
            for (int j = 0; j < 8; j++) o[i][j] *= fac;
            *(float4*)(Ps + lrow * 64 + (tx << 2)) = make_float4(p0, p1, p2, p3);
        }
        __syncthreads();

#pragma unroll 4
        for (int k = 0; k < 64; ++k) {
            float p0 = Ps[((ty << 2) + 0) * 64 + k];
            float p1 = Ps[((ty << 2) + 1) * 64 + k];
            float p2 = Ps[((ty << 2) + 2) * 64 + k];
            float p3 = Ps[((ty << 2) + 3) * 64 + k];
            float4 va = *(const float4*)(Vs + k * 132 + (tx << 3));
            float4 vb = *(const float4*)(Vs + k * 132 + (tx << 3) + 4);
            o[0][0] = fmaf(p0, va.x, o[0][0]); o[0][1] = fmaf(p0, va.y, o[0][1]);
            o[0][2] = fmaf(p0, va.z, o[0][2]); o[0][3] = fmaf(p0, va.w, o[0][3]);
            o[0][4] = fmaf(p0, vb.x, o[0][4]); o[0][5] = fmaf(p0, vb.y, o[0][5]);
            o[0][6] = fmaf(p0, vb.z, o[0][6]); o[0][7] = fmaf(p0, vb.w, o[0][7]);
            o[1][0] = fmaf(p1, va.x, o[1][0]); o[1][1] = fmaf(p1, va.y, o[1][1]);
            o[1][2] = fmaf(p1, va.z, o[1][2]); o[1][3] = fmaf(p1, va.w, o[1][3]);
            o[1][4] = fmaf(p1, vb.x, o[1][4]); o[1][5] = fmaf(p1, vb.y, o[1][5]);
            o[1][6] = fmaf(p1, vb.z, o[1][6]); o[1][7] = fmaf(p1, vb.w, o[1][7]);
            o[2][0] = fmaf(p2, va.x, o[2][0]); o[2][1] = fmaf(p2, va.y, o[2][1]);
            o[2][2] = fmaf(p2, va.z, o[2][2]); o[2][3] = fmaf(p2, va.w, o[2][3]);
            o[2][4] = fmaf(p2, vb.x, o[2][4]); o[2][5] = fmaf(p2, vb.y, o[2][5]);
            o[2][6] = fmaf(p2, vb.z, o[2][6]); o[2][7] = fmaf(p2, vb.w, o[2][7]);
            o[3][0] = fmaf(p3, va.x, o[3][0]); o[3][1] = fmaf(p3, va.y, o[3][1]);
            o[3][2] = fmaf(p3, va.z, o[3][2]); o[3][3] = fmaf(p3, va.w, o[3][3]);
            o[3][4] = fmaf(p3, vb.x, o[3][4]); o[3][5] = fmaf(p3, vb.y, o[3][5]);
            o[3][6] = fmaf(p3, vb.z, o[3][6]); o[3][7] = fmaf(p3, vb.w, o[3][7]);
        }
        __syncthreads();
    }

#pragma unroll
    for (int i = 0; i < 4; i++) {
        float inv = 1.0f / lsum[i];
        float* orow = Oo + ((size_t)(b * SS + q0 + (ty << 2) + i) * NHH + h) * VHDD + (tx << 3);
        *(float4*)orow       = make_float4(o[i][0] * inv, o[i][1] * inv, o[i][2] * inv, o[i][3] * inv);
        *(float4*)(orow + 4) = make_float4(o[i][4] * inv, o[i][5] * inv, o[i][6] * inv, o[i][7] * inv);
    }
}

// ============================================================================
// launch
// ============================================================================
extern "C" void kernel_launch(void* const* d_in, const int* in_sizes, int n_in,
                              void* d_out, int out_size)
{
    const float* x         = (const float*)d_in[0];
    const float* fcos      = (const float*)d_in[1];
    const float* fsin      = (const float*)d_in[2];
    const float* wq_a_w    = (const float*)d_in[3];
    const float* wq_a_b    = (const float*)d_in[4];
    const float* q_norm_w  = (const float*)d_in[5];
    const float* wq_b_w    = (const float*)d_in[6];
    const float* wq_b_b    = (const float*)d_in[7];
    const float* wkv_a_w   = (const float*)d_in[8];
    const float* wkv_a_b   = (const float*)d_in[9];
    const float* kv_norm_w = (const float*)d_in[10];
    const float* wkv_b_w   = (const float*)d_in[11];
    const float* wkv_b_b   = (const float*)d_in[12];
    const float* wo_w      = (const float*)d_in[13];
    const float* wo_b      = (const float*)d_in[14];
    float* out = (float*)d_out;

    float *qa, *q, *kva, *kv, *ao;
    cudaGetSymbolAddress((void**)&qa,  g_qa);
    cudaGetSymbolAddress((void**)&q,   g_q);
    cudaGetSymbolAddress((void**)&kva, g_kva);
    cudaGetSymbolAddress((void**)&kv,  g_kv);
    cudaGetSymbolAddress((void**)&ao,  g_ao);

    cudaFuncSetAttribute(sgemm_hmma, cudaFuncAttributeMaxDynamicSharedMemorySize, GEMM_SMEM);
    cudaFuncSetAttribute(flash_attn, cudaFuncAttributeMaxDynamicSharedMemorySize, (int)FLASH_SMEM);

    // 1) qa = x @ wq_a^T + b         (4096 x 1536, K=2048)
    sgemm_hmma<<<dim3(QLORA / 128, ROWS / 128), 256, GEMM_SMEM>>>(x, DIMD, wq_a_w, wq_a_b, qa, QLORA, DIMD);
    // 2) kva = x @ wkv_a^T + b       (4096 x 576, K=2048)
    sgemm_hmma<<<dim3((KVAW + 127) / 128, ROWS / 128), 256, GEMM_SMEM>>>(x, DIMD, wkv_a_w, wkv_a_b, kva, KVAW, DIMD);
    // 3) rmsnorm(qa) over 1536
    rmsnorm_k<<<ROWS, 256>>>(qa, q_norm_w, QLORA, QLORA);
    // 4) rmsnorm(kv_c) over first 512 of each 576-row
    rmsnorm_k<<<ROWS, 256>>>(kva, kv_norm_w, KVAW, KVLORA);
    // 5) rope on k_pe
    rope_kpe_k<<<(BB * SS * 32) / 256, 256>>>(kva, fcos, fsin);
    // 6) q = qa @ wq_b^T + b         (4096 x 3072, K=1536)
    sgemm_hmma<<<dim3((NHH * QKHD) / 128, ROWS / 128), 256, GEMM_SMEM>>>(qa, QLORA, wq_b_w, wq_b_b, q, NHH * QKHD, QLORA);
    // 7) rope on q_pe
    rope_q_k<<<(BB * SS * NHH * 32) / 256, 256>>>(q, fcos, fsin);
    // 8) kv = rmsnorm(kv_c) @ wkv_b^T + b   (4096 x 4096, K=512, lda=576)
    sgemm_hmma<<<dim3((NHH * (NOPED + VHDD)) / 128, ROWS / 128), 256, GEMM_SMEM>>>(kva, KVAW, wkv_b_w, wkv_b_b, kv, NHH * (NOPED + VHDD), KVLORA);
    // 9) causal flash attention -> ao
    flash_attn<<<dim3(SS / 64, NHH, BB), 256, FLASH_SMEM>>>(q, kv, kva, ao);
    // 10) out = ao @ wo^T + b        (4096 x 2048, K=2048)
    sgemm_hmma<<<dim3(DIMD / 128, ROWS / 128), 256, GEMM_SMEM>>>(ao, NHH * VHDD, wo_w, wo_b, out, DIMD, DIMD);
}

// round 7
// speedup vs baseline: 2.1475x; 1.5017x over previous
#include <cuda_runtime.h>
#include <cuda_bf16.h>
#include <cstdint>
#include <math.h>

// ---------------- problem constants ----------------
#define BB      2
#define SS      2048
#define DIMD    2048
#define NHH     16
#define QLORA   1536
#define KVLORA  512
#define ROPED   64
#define NOPED   128
#define VHDD    128
#define QKHD    192
#define KVAW    576
#define ROWS    (BB*SS)
#define SCALE_V 0.07216878364870323f

// ---------------- scratch (device globals) ----------------
// fp32 intermediates
__device__ float g_qa [ROWS * QLORA];
__device__ float g_q  [ROWS * (NHH*QKHD)];
__device__ float g_kva[ROWS * KVAW];
__device__ float g_kv [ROWS * (NHH*(NOPED+VHDD))];
// bf16 hi/lo packed (uint32 = 2 bf16), K-major pairs
__device__ uint32_t g_xh  [ROWS * 1024];     // x            [4096][2048/2]
__device__ uint32_t g_xl  [ROWS * 1024];
__device__ uint32_t g_wh  [2359296];          // weight buf (max wq_b 3072*1536/2)
__device__ uint32_t g_wl  [2359296];
__device__ uint32_t g_qah [ROWS * 768];       // rmsnorm(qa)  [4096][1536/2]
__device__ uint32_t g_qal [ROWS * 768];
__device__ uint32_t g_kvah[ROWS * 256];       // rmsnorm(kvc) [4096][512/2]
__device__ uint32_t g_kval[ROWS * 256];
__device__ uint32_t g_qbh [ROWS * NHH * 96];  // Q roped      [b,s,h][192/2]
__device__ uint32_t g_qbl [ROWS * NHH * 96];
__device__ uint32_t g_kbh [ROWS * NHH * 96];  // K assembled  [b,s,h][192/2]
__device__ uint32_t g_kbl [ROWS * NHH * 96];
__device__ uint32_t g_vbh [BB * NHH * VHDD * (SS/2)]; // V transposed [b,h,vd][S/2]
__device__ uint32_t g_vbl [BB * NHH * VHDD * (SS/2)];
__device__ uint32_t g_aoh [ROWS * 1024];      // attn out     [4096][2048/2]
__device__ uint32_t g_aol [ROWS * 1024];

// ============================================================================
// helpers
// ============================================================================
__device__ __forceinline__ uint32_t pack_bf(float a, float b) {
    uint16_t lo16 = __bfloat16_as_ushort(__float2bfloat16_rn(a));
    uint16_t hi16 = __bfloat16_as_ushort(__float2bfloat16_rn(b));
    return (uint32_t)lo16 | ((uint32_t)hi16 << 16);
}
__device__ __forceinline__ void split2(float a, float b, uint32_t& hi, uint32_t& lo) {
    float ha = __bfloat162float(__float2bfloat16_rn(a));
    float hb = __bfloat162float(__float2bfloat16_rn(b));
    hi = pack_bf(a, b);
    lo = pack_bf(a - ha, b - hb);
}
__device__ __forceinline__ void cvt_split4(float4 v, uint2& hi, uint2& lo) {
    split2(v.x, v.y, hi.x, lo.x);
    split2(v.z, v.w, hi.y, lo.y);
}
__device__ __forceinline__ void mma16816(float* d, const uint32_t* a, const uint32_t* b) {
    asm volatile(
        "mma.sync.aligned.m16n8k16.row.col.f32.bf16.bf16.f32 "
        "{%0,%1,%2,%3}, {%4,%5,%6,%7}, {%8,%9}, {%0,%1,%2,%3};"
        : "+f"(d[0]), "+f"(d[1]), "+f"(d[2]), "+f"(d[3])
        : "r"(a[0]), "r"(a[1]), "r"(a[2]), "r"(a[3]), "r"(b[0]), "r"(b[1]));
}

// ============================================================================
// conversion / prep kernels
// ============================================================================
__global__ void cvt_split_k(const float* __restrict__ in,
                            uint32_t* __restrict__ oh, uint32_t* __restrict__ ol, int n4)
{
    int i = blockIdx.x * blockDim.x + threadIdx.x;
    if (i < n4) {
        float4 v = *(const float4*)(in + 4 * (size_t)i);
        uint2 hi, lo; cvt_split4(v, hi, lo);
        *(uint2*)(oh + 2 * (size_t)i) = hi;
        *(uint2*)(ol + 2 * (size_t)i) = lo;
    }
}

__global__ __launch_bounds__(256) void rmsnorm_split_k(
    const float* __restrict__ x, const float* __restrict__ w, int stride, int n,
    uint32_t* __restrict__ oh, uint32_t* __restrict__ ol)
{
    const float* row = x + (size_t)blockIdx.x * stride;
    float ss = 0.f;
    for (int i = threadIdx.x * 4; i < n; i += 1024) {
        float4 v = *(const float4*)(row + i);
        ss += v.x * v.x + v.y * v.y + v.z * v.z + v.w * v.w;
    }
#pragma unroll
    for (int off = 16; off; off >>= 1) ss += __shfl_xor_sync(0xffffffffu, ss, off);
    __shared__ float ws[8];
    if ((threadIdx.x & 31) == 0) ws[threadIdx.x >> 5] = ss;
    __syncthreads();
    float tot = 0.f;
#pragma unroll
    for (int i = 0; i < 8; i++) tot += ws[i];
    float r = rsqrtf(tot / (float)n + 1e-6f);
    const int ow = n >> 1;
    for (int i = threadIdx.x * 4; i < n; i += 1024) {
        float4 v  = *(const float4*)(row + i);
        float4 wv = *(const float4*)(w + i);
        v.x *= r * wv.x; v.y *= r * wv.y; v.z *= r * wv.z; v.w *= r * wv.w;
        uint2 hi, lo; cvt_split4(v, hi, lo);
        *(uint2*)(oh + (size_t)blockIdx.x * ow + (i >> 1)) = hi;
        *(uint2*)(ol + (size_t)blockIdx.x * ow + (i >> 1)) = lo;
    }
}

// rope on k_pe in g_kva (fp32, cols 512..575)
__global__ void rope_kpe_k(float* __restrict__ kva,
                           const float* __restrict__ cosd, const float* __restrict__ sind)
{
    int idx = blockIdx.x * blockDim.x + threadIdx.x;
    int i = idx & 31;
    int s = (idx >> 5) & 2047;
    int b = idx >> 16;
    float* p = kva + (size_t)(b * SS + s) * KVAW + KVLORA + 2 * i;
    float c = cosd[s * 32 + i], sn = sind[s * 32 + i];
    float xr = p[0], xi = p[1];
    p[0] = xr * c - xi * sn;
    p[1] = xr * sn + xi * c;
}

// q fp32 [b,s,h,192] -> roped + split to pair-words
__global__ void cvt_q_rope_k(const float* __restrict__ q,
                             const float* __restrict__ cosd, const float* __restrict__ sind,
                             uint32_t* __restrict__ oh, uint32_t* __restrict__ ol)
{
    int i = blockIdx.x * blockDim.x + threadIdx.x;
    if (i >= ROWS * NHH * 96) return;
    int p = i % 96;
    int s = (i / (96 * NHH)) % SS;
    float2 v = *(const float2*)(q + 2 * (size_t)i);
    if (p >= 64) {
        int ri = p - 64;
        float c = cosd[s * 32 + ri], sn = sind[s * 32 + ri];
        float xr = v.x, xi = v.y;
        v.x = xr * c - xi * sn;
        v.y = xr * sn + xi * c;
    }
    uint32_t hi, lo; split2(v.x, v.y, hi, lo);
    oh[i] = hi; ol[i] = lo;
}

// K = concat(kv[...,0:128], kpe) -> split pair-words [b,s,h][96]
__global__ void assemble_k_k(const float* __restrict__ kv, const float* __restrict__ kva,
                             uint32_t* __restrict__ oh, uint32_t* __restrict__ ol)
{
    int i = blockIdx.x * blockDim.x + threadIdx.x;
    if (i >= ROWS * NHH * 96) return;
    int p = i % 96;
    int r = i / 96;              // (b*S+s)*NH + h
    int bs = r / NHH;
    float2 v;
    if (p < 64) v = *(const float2*)(kv + (size_t)r * 256 + 2 * p);
    else        v = *(const float2*)(kva + (size_t)bs * KVAW + KVLORA + 2 * (p - 64));
    uint32_t hi, lo; split2(v.x, v.y, hi, lo);
    oh[i] = hi; ol[i] = lo;
}

// V transpose: kv[b,s,h,128+vd] -> vb[b,h,vd][s/2] pair-words (pairs along s)
__global__ __launch_bounds__(256) void assemble_v_k(const float* __restrict__ kv,
                             uint32_t* __restrict__ oh, uint32_t* __restrict__ ol)
{
    extern __shared__ float sm[];   // [128][129]
    int sc = blockIdx.x, h = blockIdx.y, b = blockIdx.z;
    int tid = threadIdx.x;
    for (int f = tid; f < 128 * 32; f += 256) {
        int r = f >> 5, c4 = f & 31;
        float4 v = *(const float4*)(kv + ((size_t)((b * SS + sc * 128 + r) * NHH + h)) * 256 + 128 + c4 * 4);
        sm[r * 129 + c4 * 4 + 0] = v.x;
        sm[r * 129 + c4 * 4 + 1] = v.y;
        sm[r * 129 + c4 * 4 + 2] = v.z;
        sm[r * 129 + c4 * 4 + 3] = v.w;
    }
    __syncthreads();
    for (int w = tid; w < 128 * 64; w += 256) {
        int vd = w >> 6, kp = w & 63;
        float a = sm[(2 * kp) * 129 + vd];
        float c = sm[(2 * kp + 1) * 129 + vd];
        uint32_t hi, lo; split2(a, c, hi, lo);
        size_t oidx = ((size_t)((b * NHH + h) * VHDD + vd)) * (SS / 2) + sc * 64 + kp;
        oh[oidx] = hi; ol[oidx] = lo;
    }
}

// ============================================================================
// HMMA GEMM: C[M,N] = A @ W^T + bias. A,W pre-split bf16 hi/lo pair-words.
// CTA 128x128, 8 warps (2x4), K-chunk 32, double-buffered. smem stride 20 wrds.
// ============================================================================
#define ASZW   2560
#define STAGEW (4*ASZW)
#define GEMM_SMEM (2*STAGEW*4)

__global__ __launch_bounds__(256, 1) void gemm_hmma(
    const uint32_t* __restrict__ Ah_, const uint32_t* __restrict__ Al_, int ldaw,
    const uint32_t* __restrict__ Bh_, const uint32_t* __restrict__ Bl_,
    const float* __restrict__ bias,
    float* __restrict__ C, int N, int K)
{
    extern __shared__ uint32_t smw[];
    const int tid  = threadIdx.x;
    const int lane = tid & 31;
    const int wid  = tid >> 5;
    const int warp_m = wid & 1;
    const int warp_n = wid >> 1;
    const int bm = blockIdx.y * 128;
    const int bn = blockIdx.x * 128;
    const int t = lane & 3;
    const int g = lane >> 2;
    const int ldbw = K >> 1;
    const int nc = K >> 5;

    const int lr = tid >> 2;       // 0..63  (rows lr, lr+64)
    const int lq = tid & 3;        // word quad
    const bool bv0 = (bn + lr) < N;
    const bool bv1 = (bn + lr + 64) < N;

    float acc[4][4][4];
#pragma unroll
    for (int i = 0; i < 4; i++)
#pragma unroll
        for (int j = 0; j < 4; j++)
#pragma unroll
            for (int k = 0; k < 4; k++) acc[i][j][k] = 0.f;

    uint4 pah[2], pal[2], pbh[2], pbl[2];
    const uint4 z4 = make_uint4(0, 0, 0, 0);

    // prologue: chunk 0 -> regs -> smem stage 0
#pragma unroll
    for (int i = 0; i < 2; ++i) {
        int row = lr + i * 64;
        pah[i] = *(const uint4*)(Ah_ + (size_t)(bm + row) * ldaw + lq * 4);
        pal[i] = *(const uint4*)(Al_ + (size_t)(bm + row) * ldaw + lq * 4);
        bool bv = i ? bv1 : bv0;
        pbh[i] = bv ? *(const uint4*)(Bh_ + (size_t)(bn + row) * ldbw + lq * 4) : z4;
        pbl[i] = bv ? *(const uint4*)(Bl_ + (size_t)(bn + row) * ldbw + lq * 4) : z4;
    }
    {
        uint32_t* st = smw;
#pragma unroll
        for (int i = 0; i < 2; ++i) {
            int row = lr + i * 64;
            int widx = row * 20 + lq * 4;
            *(uint4*)(st + widx)            = pah[i];
            *(uint4*)(st + ASZW + widx)     = pal[i];
            *(uint4*)(st + 2 * ASZW + widx) = pbh[i];
            *(uint4*)(st + 3 * ASZW + widx) = pbl[i];
        }
    }
    __syncthreads();

    for (int ck = 0; ck < nc; ++ck) {
        if (ck + 1 < nc) {
            const int k0w = (ck + 1) << 4;
#pragma unroll
            for (int i = 0; i < 2; ++i) {
                int row = lr + i * 64;
                pah[i] = *(const uint4*)(Ah_ + (size_t)(bm + row) * ldaw + k0w + lq * 4);
                pal[i] = *(const uint4*)(Al_ + (size_t)(bm + row) * ldaw + k0w + lq * 4);
                bool bv = i ? bv1 : bv0;
                pbh[i] = bv ? *(const uint4*)(Bh_ + (size_t)(bn + row) * ldbw + k0w + lq * 4) : z4;
                pbl[i] = bv ? *(const uint4*)(Bl_ + (size_t)(bn + row) * ldbw + k0w + lq * 4) : z4;
            }
        }
        // compute current stage
        {
            uint32_t* Ah = smw + (ck & 1) * STAGEW;
            uint32_t* Al = Ah + ASZW;
            uint32_t* Bh = Ah + 2 * ASZW;
            uint32_t* Bl = Ah + 3 * ASZW;
#pragma unroll
            for (int k16 = 0; k16 < 2; ++k16) {
                const int kp = k16 * 8;
                uint32_t bh[4][2], bl[4][2];
#pragma unroll
                for (int nt = 0; nt < 4; ++nt) {
                    int idx = (warp_n * 32 + nt * 8 + g) * 20 + kp + t;
                    bh[nt][0] = Bh[idx]; bh[nt][1] = Bh[idx + 4];
                    bl[nt][0] = Bl[idx]; bl[nt][1] = Bl[idx + 4];
                }
#pragma unroll
                for (int mt = 0; mt < 4; ++mt) {
                    int base = (warp_m * 64 + mt * 16 + g) * 20 + kp + t;
                    uint32_t ah[4], al[4];
                    ah[0] = Ah[base];     ah[1] = Ah[base + 160];
                    ah[2] = Ah[base + 4]; ah[3] = Ah[base + 164];
                    al[0] = Al[base];     al[1] = Al[base + 160];
                    al[2] = Al[base + 4]; al[3] = Al[base + 164];
#pragma unroll
                    for (int nt = 0; nt < 4; ++nt) {
                        mma16816(acc[mt][nt], ah, bh[nt]);
                        mma16816(acc[mt][nt], ah, bl[nt]);
                        mma16816(acc[mt][nt], al, bh[nt]);
                    }
                }
            }
        }
        if (ck + 1 < nc) {
            uint32_t* st = smw + ((ck + 1) & 1) * STAGEW;
#pragma unroll
            for (int i = 0; i < 2; ++i) {
                int row = lr + i * 64;
                int widx = row * 20 + lq * 4;
                *(uint4*)(st + widx)            = pah[i];
                *(uint4*)(st + ASZW + widx)     = pal[i];
                *(uint4*)(st + 2 * ASZW + widx) = pbh[i];
                *(uint4*)(st + 3 * ASZW + widx) = pbl[i];
            }
        }
        __syncthreads();
    }

#pragma unroll
    for (int mt = 0; mt < 4; ++mt) {
        int r0 = bm + warp_m * 64 + mt * 16 + g;
#pragma unroll
        for (int nt = 0; nt < 4; ++nt) {
            int c = bn + warp_n * 32 + nt * 8 + t * 2;
            if (c < N) {
                float2 bv = *(const float2*)(bias + c);
                *(float2*)(C + (size_t)r0 * N + c)       = make_float2(acc[mt][nt][0] + bv.x, acc[mt][nt][1] + bv.y);
                *(float2*)(C + (size_t)(r0 + 8) * N + c) = make_float2(acc[mt][nt][2] + bv.x, acc[mt][nt][3] + bv.y);
            }
        }
    }
}

// ============================================================================
// HMMA flash attention (causal). q-tile 64, k-tile 64, 8 warps (4x2).
// All operands pre-split bf16 hi/lo pair-words. 3-pass everywhere.
// ============================================================================
#define FL_QS   0
#define FL_QSL  6400
#define FL_KS   12800
#define FL_KSL  19200
#define FL_VS   25600
#define FL_VSL  30208
#define FL_PS   34816
#define FL_PSL  37120
#define FL_RM   39424
#define FL_RL   39552
#define FL_WORDS 39680
#define FLASH_SMEM (FL_WORDS*4)

__global__ __launch_bounds__(256, 1) void flash_hmma(
    const uint32_t* __restrict__ qh_, const uint32_t* __restrict__ ql_,
    const uint32_t* __restrict__ kh_, const uint32_t* __restrict__ kl_,
    const uint32_t* __restrict__ vh_, const uint32_t* __restrict__ vl_,
    uint32_t* __restrict__ aoh, uint32_t* __restrict__ aol)
{
    extern __shared__ uint32_t sw[];
    float* redm = (float*)(sw + FL_RM);
    float* redl = (float*)(sw + FL_RL);
    const int tid = threadIdx.x;
    const int lane = tid & 31;
    const int wid = tid >> 5;
    const int wm = wid & 3, wn = wid >> 2;
    const int g = lane >> 2, t = lane & 3;
    const int qt = (int)(gridDim.x - 1) - (int)blockIdx.x;
    const int h = blockIdx.y, b = blockIdx.z;
    const int q0 = qt * 64;
    const int row0 = wm * 16 + g, row1 = row0 + 8;

    // load Q tile (once)
    {
        int r = tid >> 2, qq = tid & 3;
        size_t gb = ((size_t)((b * SS + q0 + r) * NHH + h)) * 96 + qq * 24;
#pragma unroll
        for (int j = 0; j < 6; ++j) {
            *(uint4*)(sw + FL_QS  + r * 100 + qq * 24 + j * 4) = *(const uint4*)(qh_ + gb + j * 4);
            *(uint4*)(sw + FL_QSL + r * 100 + qq * 24 + j * 4) = *(const uint4*)(ql_ + gb + j * 4);
        }
    }

    float o[8][4];
#pragma unroll
    for (int i = 0; i < 8; i++)
#pragma unroll
        for (int j = 0; j < 4; j++) o[i][j] = 0.f;
    float mold0 = -1e30f, mold1 = -1e30f, ls0 = 0.f, ls1 = 0.f;

    for (int kt = 0; kt <= qt; ++kt) {
        const int k0 = kt * 64;
        __syncthreads();   // prev PV done; Ks/Vs/Ps free
        // load K tile
        {
            int r = tid >> 2, qq = tid & 3;
            size_t gb = ((size_t)((b * SS + k0 + r) * NHH + h)) * 96 + qq * 24;
#pragma unroll
            for (int j = 0; j < 6; ++j) {
                *(uint4*)(sw + FL_KS  + r * 100 + qq * 24 + j * 4) = *(const uint4*)(kh_ + gb + j * 4);
                *(uint4*)(sw + FL_KSL + r * 100 + qq * 24 + j * 4) = *(const uint4*)(kl_ + gb + j * 4);
            }
            // V tile: rows=vd(128), 32 pair-words each
            int vd = tid >> 1, pt = tid & 1;
            size_t vb = ((size_t)((b * NHH + h) * VHDD + vd)) * (SS / 2) + kt * 32 + pt * 16;
#pragma unroll
            for (int j = 0; j < 4; ++j) {
                *(uint4*)(sw + FL_VS  + vd * 36 + pt * 16 + j * 4) = *(const uint4*)(vh_ + vb + j * 4);
                *(uint4*)(sw + FL_VSL + vd * 36 + pt * 16 + j * 4) = *(const uint4*)(vl_ + vb + j * 4);
            }
        }
        __syncthreads();

        // ---- scores: S[64x64], warp tile 16x32
        float sacc[4][4];
#pragma unroll
        for (int i = 0; i < 4; i++)
#pragma unroll
            for (int j = 0; j < 4; j++) sacc[i][j] = 0.f;
#pragma unroll
        for (int ks = 0; ks < 12; ++ks) {
            int aq = (wm * 16 + g) * 100 + ks * 8 + t;
            uint32_t ah[4], al[4];
            ah[0] = sw[FL_QS + aq];       ah[1] = sw[FL_QS + aq + 800];
            ah[2] = sw[FL_QS + aq + 4];   ah[3] = sw[FL_QS + aq + 804];
            al[0] = sw[FL_QSL + aq];      al[1] = sw[FL_QSL + aq + 800];
            al[2] = sw[FL_QSL + aq + 4];  al[3] = sw[FL_QSL + aq + 804];
#pragma unroll
            for (int nt = 0; nt < 4; ++nt) {
                int bi = (wn * 32 + nt * 8 + g) * 100 + ks * 8 + t;
                uint32_t bh[2] = { sw[FL_KS + bi],  sw[FL_KS + bi + 4] };
                uint32_t bl[2] = { sw[FL_KSL + bi], sw[FL_KSL + bi + 4] };
                mma16816(sacc[nt], ah, bh);
                mma16816(sacc[nt], ah, bl);
                mma16816(sacc[nt], al, bh);
            }
        }

        // scale + causal mask (diag tile only)
        const bool diag = (kt == qt);
#pragma unroll
        for (int nt = 0; nt < 4; ++nt) {
            sacc[nt][0] *= SCALE_V; sacc[nt][1] *= SCALE_V;
            sacc[nt][2] *= SCALE_V; sacc[nt][3] *= SCALE_V;
            if (diag) {
                int c0 = wn * 32 + nt * 8 + 2 * t;
                if (c0 > row0)     sacc[nt][0] = -1e30f;
                if (c0 + 1 > row0) sacc[nt][1] = -1e30f;
                if (c0 > row1)     sacc[nt][2] = -1e30f;
                if (c0 + 1 > row1) sacc[nt][3] = -1e30f;
            }
        }

        // row max (intra-warp over 32 cols)
        float m0 = -1e30f, m1 = -1e30f;
#pragma unroll
        for (int nt = 0; nt < 4; ++nt) {
            m0 = fmaxf(m0, fmaxf(sacc[nt][0], sacc[nt][1]));
            m1 = fmaxf(m1, fmaxf(sacc[nt][2], sacc[nt][3]));
        }
        m0 = fmaxf(m0, __shfl_xor_sync(0xffffffffu, m0, 1));
        m0 = fmaxf(m0, __shfl_xor_sync(0xffffffffu, m0, 2));
        m1 = fmaxf(m1, __shfl_xor_sync(0xffffffffu, m1, 1));
        m1 = fmaxf(m1, __shfl_xor_sync(0xffffffffu, m1, 2));
        if (t == 0) { redm[wn * 64 + row0] = m0; redm[wn * 64 + row1] = m1; }
        __syncthreads();

        float mnew0 = fmaxf(mold0, fmaxf(redm[row0], redm[64 + row0]));
        float mnew1 = fmaxf(mold1, fmaxf(redm[row1], redm[64 + row1]));
        float fac0 = __expf(mold0 - mnew0);
        float fac1 = __expf(mold1 - mnew1);
        mold0 = mnew0; mold1 = mnew1;

        float sum0 = 0.f, sum1 = 0.f;
#pragma unroll
        for (int nt = 0; nt < 4; ++nt) {
            float p0 = __expf(sacc[nt][0] - mnew0);
            float p1 = __expf(sacc[nt][1] - mnew0);
            float p2 = __expf(sacc[nt][2] - mnew1);
            float p3 = __expf(sacc[nt][3] - mnew1);
            sum0 += p0 + p1; sum1 += p2 + p3;
            uint32_t hi, lo;
            split2(p0, p1, hi, lo);
            sw[FL_PS  + row0 * 36 + wn * 16 + nt * 4 + t] = hi;
            sw[FL_PSL + row0 * 36 + wn * 16 + nt * 4 + t] = lo;
            split2(p2, p3, hi, lo);
            sw[FL_PS  + row1 * 36 + wn * 16 + nt * 4 + t] = hi;
            sw[FL_PSL + row1 * 36 + wn * 16 + nt * 4 + t] = lo;
        }
        sum0 += __shfl_xor_sync(0xffffffffu, sum0, 1);
        sum0 += __shfl_xor_sync(0xffffffffu, sum0, 2);
        sum1 += __shfl_xor_sync(0xffffffffu, sum1, 1);
        sum1 += __shfl_xor_sync(0xffffffffu, sum1, 2);
        if (t == 0) { redl[wn * 64 + row0] = sum0; redl[wn * 64 + row1] = sum1; }

        // rescale O
#pragma unroll
        for (int nt = 0; nt < 8; ++nt) {
            o[nt][0] *= fac0; o[nt][1] *= fac0;
            o[nt][2] *= fac1; o[nt][3] *= fac1;
        }
        __syncthreads();

        ls0 = ls0 * fac0 + redl[row0] + redl[64 + row0];
        ls1 = ls1 * fac1 + redl[row1] + redl[64 + row1];

        // ---- PV: O[64x128] += P[64x64] @ V; warp tile 16x64
#pragma unroll
        for (int ks = 0; ks < 4; ++ks) {
            int pb = (wm * 16 + g) * 36 + ks * 8 + t;
            uint32_t ah[4], al[4];
            ah[0] = sw[FL_PS + pb];       ah[1] = sw[FL_PS + pb + 288];
            ah[2] = sw[FL_PS + pb + 4];   ah[3] = sw[FL_PS + pb + 292];
            al[0] = sw[FL_PSL + pb];      al[1] = sw[FL_PSL + pb + 288];
            al[2] = sw[FL_PSL + pb + 4];  al[3] = sw[FL_PSL + pb + 292];
#pragma unroll
            for (int nt = 0; nt < 8; ++nt) {
                int vi = (wn * 64 + nt * 8 + g) * 36 + ks * 8 + t;
                uint32_t bh[2] = { sw[FL_VS + vi],  sw[FL_VS + vi + 4] };
                uint32_t bl[2] = { sw[FL_VSL + vi], sw[FL_VSL + vi + 4] };
                mma16816(o[nt], ah, bh);
                mma16816(o[nt], ah, bl);
                mma16816(o[nt], al, bh);
            }
        }
    }

    // epilogue: normalize, split, write bf16 hi/lo pair-words
    float inv0 = 1.0f / ls0, inv1 = 1.0f / ls1;
    size_t r0 = (size_t)(b * SS + q0 + row0) * 1024;
    size_t r1 = (size_t)(b * SS + q0 + row1) * 1024;
#pragma unroll
    for (int nt = 0; nt < 8; ++nt) {
        int word = h * 64 + wn * 32 + nt * 4 + t;
        uint32_t hi, lo;
        split2(o[nt][0] * inv0, o[nt][1] * inv0, hi, lo);
        aoh[r0 + word] = hi; aol[r0 + word] = lo;
        split2(o[nt][2] * inv1, o[nt][3] * inv1, hi, lo);
        aoh[r1 + word] = hi; aol[r1 + word] = lo;
    }
}

// ============================================================================
// launch
// ============================================================================
extern "C" void kernel_launch(void* const* d_in, const int* in_sizes, int n_in,
                              void* d_out, int out_size)
{
    const float* x         = (const float*)d_in[0];
    const float* fcos      = (const float*)d_in[1];
    const float* fsin      = (const float*)d_in[2];
    const float* wq_a_w    = (const float*)d_in[3];
    const float* wq_a_b    = (const float*)d_in[4];
    const float* q_norm_w  = (const float*)d_in[5];
    const float* wq_b_w    = (const float*)d_in[6];
    const float* wq_b_b    = (const float*)d_in[7];
    const float* wkv_a_w   = (const float*)d_in[8];
    const float* wkv_a_b   = (const float*)d_in[9];
    const float* kv_norm_w = (const float*)d_in[10];
    const float* wkv_b_w   = (const float*)d_in[11];
    const float* wkv_b_b   = (const float*)d_in[12];
    const float* wo_w      = (const float*)d_in[13];
    const float* wo_b      = (const float*)d_in[14];
    float* out = (float*)d_out;

    float *qa, *q, *kva, *kv;
    uint32_t *xh, *xl, *wh, *wl, *qah, *qal, *kvah, *kval;
    uint32_t *qbh, *qbl, *kbh, *kbl, *vbh, *vbl, *aoh, *aol;
    cudaGetSymbolAddress((void**)&qa,   g_qa);
    cudaGetSymbolAddress((void**)&q,    g_q);
    cudaGetSymbolAddress((void**)&kva,  g_kva);
    cudaGetSymbolAddress((void**)&kv,   g_kv);
    cudaGetSymbolAddress((void**)&xh,   g_xh);
    cudaGetSymbolAddress((void**)&xl,   g_xl);
    cudaGetSymbolAddress((void**)&wh,   g_wh);
    cudaGetSymbolAddress((void**)&wl,   g_wl);
    cudaGetSymbolAddress((void**)&qah,  g_qah);
    cudaGetSymbolAddress((void**)&qal,  g_qal);
    cudaGetSymbolAddress((void**)&kvah, g_kvah);
    cudaGetSymbolAddress((void**)&kval, g_kval);
    cudaGetSymbolAddress((void**)&qbh,  g_qbh);
    cudaGetSymbolAddress((void**)&qbl,  g_qbl);
    cudaGetSymbolAddress((void**)&kbh,  g_kbh);
    cudaGetSymbolAddress((void**)&kbl,  g_kbl);
    cudaGetSymbolAddress((void**)&vbh,  g_vbh);
    cudaGetSymbolAddress((void**)&vbl,  g_vbl);
    cudaGetSymbolAddress((void**)&aoh,  g_aoh);
    cudaGetSymbolAddress((void**)&aol,  g_aol);

    cudaFuncSetAttribute(gemm_hmma,   cudaFuncAttributeMaxDynamicSharedMemorySize, GEMM_SMEM);
    cudaFuncSetAttribute(flash_hmma,  cudaFuncAttributeMaxDynamicSharedMemorySize, FLASH_SMEM);
    cudaFuncSetAttribute(assemble_v_k, cudaFuncAttributeMaxDynamicSharedMemorySize, 128 * 129 * 4);

    #define CVT(src, dh, dl, n) cvt_split_k<<<((n)/4 + 255)/256, 256>>>(src, dh, dl, (n)/4)

    // x -> bf16 hi/lo
    CVT(x, xh, xl, ROWS * DIMD);
    // gemm1: qa = x @ wq_a^T + b
    CVT(wq_a_w, wh, wl, QLORA * DIMD);
    gemm_hmma<<<dim3(QLORA/128, ROWS/128), 256, GEMM_SMEM>>>(xh, xl, DIMD/2, wh, wl, wq_a_b, qa, QLORA, DIMD);
    // gemm2: kva = x @ wkv_a^T + b
    CVT(wkv_a_w, wh, wl, KVAW * DIMD);
    gemm_hmma<<<dim3((KVAW+127)/128, ROWS/128), 256, GEMM_SMEM>>>(xh, xl, DIMD/2, wh, wl, wkv_a_b, kva, KVAW, DIMD);
    // rmsnorm + split
    rmsnorm_split_k<<<ROWS, 256>>>(qa, q_norm_w, QLORA, QLORA, qah, qal);
    rmsnorm_split_k<<<ROWS, 256>>>(kva, kv_norm_w, KVAW, KVLORA, kvah, kval);
    // rope k_pe (fp32, in place)
    rope_kpe_k<<<(BB*SS*32)/256, 256>>>(kva, fcos, fsin);
    // gemm3: q = qa_n @ wq_b^T + b
    CVT(wq_b_w, wh, wl, NHH*QKHD*QLORA);
    gemm_hmma<<<dim3((NHH*QKHD)/128, ROWS/128), 256, GEMM_SMEM>>>(qah, qal, QLORA/2, wh, wl, wq_b_b, q, NHH*QKHD, QLORA);
    // rope+split q
    cvt_q_rope_k<<<(ROWS*NHH*96 + 255)/256, 256>>>(q, fcos, fsin, qbh, qbl);
    // gemm4: kv = kva_n @ wkv_b^T + b
    CVT(wkv_b_w, wh, wl, NHH*(NOPED+VHDD)*KVLORA);
    gemm_hmma<<<dim3((NHH*(NOPED+VHDD))/128, ROWS/128), 256, GEMM_SMEM>>>(kvah, kval, KVLORA/2, wh, wl, wkv_b_b, kv, NHH*(NOPED+VHDD), KVLORA);
    // K assembly + V transpose
    assemble_k_k<<<(ROWS*NHH*96 + 255)/256, 256>>>(kv, kva, kbh, kbl);
    assemble_v_k<<<dim3(SS/128, NHH, BB), 256, 128*129*4>>>(kv, vbh, vbl);
    // flash attention -> ao (bf16 hi/lo)
    flash_hmma<<<dim3(SS/64, NHH, BB), 256, FLASH_SMEM>>>(qbh, qbl, kbh, kbl, vbh, vbl, aoh, aol);
    // gemm5: out = ao @ wo^T + b
    CVT(wo_w, wh, wl, DIMD * NHH*VHDD);
    gemm_hmma<<<dim3(DIMD/128, ROWS/128), 256, GEMM_SMEM>>>(aoh, aol, (NHH*VHDD)/2, wh, wl, wo_b, out, DIMD, DIMD);
}

// round 8
// speedup vs baseline: 2.7894x; 1.2989x over previous
#include <cuda_runtime.h>
#include <cuda_bf16.h>
#include <cuda_fp16.h>
#include <cstdint>
#include <math.h>

// ---------------- problem constants ----------------
#define BB      2
#define SS      2048
#define DIMD    2048
#define NHH     16
#define QLORA   1536
#define KVLORA  512
#define ROPED   64
#define NOPED   128
#define VHDD    128
#define QKHD    192
#define KVAW    576
#define ROWS    (BB*SS)
#define SCALE_V 0.07216878364870323f

// ---------------- scratch (device globals) ----------------
__device__ float g_qa [ROWS * QLORA];
__device__ float g_q  [ROWS * (NHH*QKHD)];
__device__ float g_kva[ROWS * KVAW];
__device__ float g_kv [ROWS * (NHH*(NOPED+VHDD))];
// fp16 pair-words for GEMM operands
__device__ uint32_t g_xh  [ROWS * 1024];     // x hi        [4096][2048/2]
__device__ uint32_t g_xl  [ROWS * 1024];     // x lo
__device__ uint32_t g_wh  [2359296];          // weights fp16 (single)
__device__ uint32_t g_qah [ROWS * 768];       // rmsnorm(qa) hi/lo
__device__ uint32_t g_qal [ROWS * 768];
__device__ uint32_t g_kvah[ROWS * 256];
__device__ uint32_t g_kval[ROWS * 256];
__device__ uint32_t g_aoh [ROWS * 1024];      // attn out hi/lo (fp16)
__device__ uint32_t g_aol [ROWS * 1024];
// bf16 pair-words for flash attention
__device__ uint32_t g_qbh [ROWS * NHH * 96];
__device__ uint32_t g_qbl [ROWS * NHH * 96];
__device__ uint32_t g_kbh [ROWS * NHH * 96];
__device__ uint32_t g_kbl [ROWS * NHH * 96];
__device__ uint32_t g_vbh [BB * NHH * VHDD * (SS/2)];
__device__ uint32_t g_vbl [BB * NHH * VHDD * (SS/2)];

// ============================================================================
// helpers
// ============================================================================
// bf16 split (flash)
__device__ __forceinline__ uint32_t pack_bf(float a, float b) {
    uint16_t lo16 = __bfloat16_as_ushort(__float2bfloat16_rn(a));
    uint16_t hi16 = __bfloat16_as_ushort(__float2bfloat16_rn(b));
    return (uint32_t)lo16 | ((uint32_t)hi16 << 16);
}
__device__ __forceinline__ void split2b(float a, float b, uint32_t& hi, uint32_t& lo) {
    float ha = __bfloat162float(__float2bfloat16_rn(a));
    float hb = __bfloat162float(__float2bfloat16_rn(b));
    hi = pack_bf(a, b);
    lo = pack_bf(a - ha, b - hb);
}
// fp16 split (gemm)
__device__ __forceinline__ uint32_t pack_h(float a, float b) {
    uint16_t lo16 = __half_as_ushort(__float2half_rn(a));
    uint16_t hi16 = __half_as_ushort(__float2half_rn(b));
    return (uint32_t)lo16 | ((uint32_t)hi16 << 16);
}
__device__ __forceinline__ void split2h(float a, float b, uint32_t& hi, uint32_t& lo) {
    float ha = __half2float(__float2half_rn(a));
    float hb = __half2float(__float2half_rn(b));
    hi = pack_h(a, b);
    lo = pack_h(a - ha, b - hb);
}
__device__ __forceinline__ void cvt_split4h(float4 v, uint2& hi, uint2& lo) {
    split2h(v.x, v.y, hi.x, lo.x);
    split2h(v.z, v.w, hi.y, lo.y);
}
// bf16 mma (flash)
__device__ __forceinline__ void mma_bf(float* d, const uint32_t* a, const uint32_t* b) {
    asm volatile(
        "mma.sync.aligned.m16n8k16.row.col.f32.bf16.bf16.f32 "
        "{%0,%1,%2,%3}, {%4,%5,%6,%7}, {%8,%9}, {%0,%1,%2,%3};"
        : "+f"(d[0]), "+f"(d[1]), "+f"(d[2]), "+f"(d[3])
        : "r"(a[0]), "r"(a[1]), "r"(a[2]), "r"(a[3]), "r"(b[0]), "r"(b[1]));
}
// fp16 mma (gemm)
__device__ __forceinline__ void mma_h(float* d, const uint32_t* a, const uint32_t* b) {
    asm volatile(
        "mma.sync.aligned.m16n8k16.row.col.f32.f16.f16.f32 "
        "{%0,%1,%2,%3}, {%4,%5,%6,%7}, {%8,%9}, {%0,%1,%2,%3};"
        : "+f"(d[0]), "+f"(d[1]), "+f"(d[2]), "+f"(d[3])
        : "r"(a[0]), "r"(a[1]), "r"(a[2]), "r"(a[3]), "r"(b[0]), "r"(b[1]));
}

// ============================================================================
// conversion / prep kernels
// ============================================================================
// fp32 -> fp16 hi/lo (A operands)
__global__ void cvt_split_h_k(const float* __restrict__ in,
                              uint32_t* __restrict__ oh, uint32_t* __restrict__ ol, int n4)
{
    int i = blockIdx.x * blockDim.x + threadIdx.x;
    if (i < n4) {
        float4 v = *(const float4*)(in + 4 * (size_t)i);
        uint2 hi, lo; cvt_split4h(v, hi, lo);
        *(uint2*)(oh + 2 * (size_t)i) = hi;
        *(uint2*)(ol + 2 * (size_t)i) = lo;
    }
}
// fp32 -> fp16 single (weights)
__global__ void cvt_h_k(const float* __restrict__ in, uint32_t* __restrict__ oh, int n4)
{
    int i = blockIdx.x * blockDim.x + threadIdx.x;
    if (i < n4) {
        float4 v = *(const float4*)(in + 4 * (size_t)i);
        uint2 hi;
        hi.x = pack_h(v.x, v.y);
        hi.y = pack_h(v.z, v.w);
        *(uint2*)(oh + 2 * (size_t)i) = hi;
    }
}

__global__ __launch_bounds__(256) void rmsnorm_split_k(
    const float* __restrict__ x, const float* __restrict__ w, int stride, int n,
    uint32_t* __restrict__ oh, uint32_t* __restrict__ ol)
{
    const float* row = x + (size_t)blockIdx.x * stride;
    float ss = 0.f;
    for (int i = threadIdx.x * 4; i < n; i += 1024) {
        float4 v = *(const float4*)(row + i);
        ss += v.x * v.x + v.y * v.y + v.z * v.z + v.w * v.w;
    }
#pragma unroll
    for (int off = 16; off; off >>= 1) ss += __shfl_xor_sync(0xffffffffu, ss, off);
    __shared__ float ws[8];
    if ((threadIdx.x & 31) == 0) ws[threadIdx.x >> 5] = ss;
    __syncthreads();
    float tot = 0.f;
#pragma unroll
    for (int i = 0; i < 8; i++) tot += ws[i];
    float r = rsqrtf(tot / (float)n + 1e-6f);
    const int ow = n >> 1;
    for (int i = threadIdx.x * 4; i < n; i += 1024) {
        float4 v  = *(const float4*)(row + i);
        float4 wv = *(const float4*)(w + i);
        v.x *= r * wv.x; v.y *= r * wv.y; v.z *= r * wv.z; v.w *= r * wv.w;
        uint2 hi, lo; cvt_split4h(v, hi, lo);
        *(uint2*)(oh + (size_t)blockIdx.x * ow + (i >> 1)) = hi;
        *(uint2*)(ol + (size_t)blockIdx.x * ow + (i >> 1)) = lo;
    }
}

// rope on k_pe in g_kva (fp32, cols 512..575)
__global__ void rope_kpe_k(float* __restrict__ kva,
                           const float* __restrict__ cosd, const float* __restrict__ sind)
{
    int idx = blockIdx.x * blockDim.x + threadIdx.x;
    int i = idx & 31;
    int s = (idx >> 5) & 2047;
    int b = idx >> 16;
    float* p = kva + (size_t)(b * SS + s) * KVAW + KVLORA + 2 * i;
    float c = cosd[s * 32 + i], sn = sind[s * 32 + i];
    float xr = p[0], xi = p[1];
    p[0] = xr * c - xi * sn;
    p[1] = xr * sn + xi * c;
}

// q fp32 -> roped + bf16 split
__global__ void cvt_q_rope_k(const float* __restrict__ q,
                             const float* __restrict__ cosd, const float* __restrict__ sind,
                             uint32_t* __restrict__ oh, uint32_t* __restrict__ ol)
{
    int i = blockIdx.x * blockDim.x + threadIdx.x;
    if (i >= ROWS * NHH * 96) return;
    int p = i % 96;
    int s = (i / (96 * NHH)) % SS;
    float2 v = *(const float2*)(q + 2 * (size_t)i);
    if (p >= 64) {
        int ri = p - 64;
        float c = cosd[s * 32 + ri], sn = sind[s * 32 + ri];
        float xr = v.x, xi = v.y;
        v.x = xr * c - xi * sn;
        v.y = xr * sn + xi * c;
    }
    uint32_t hi, lo; split2b(v.x, v.y, hi, lo);
    oh[i] = hi; ol[i] = lo;
}

// K = concat(kv[...,0:128], kpe) -> bf16 split [b,s,h][96]
__global__ void assemble_k_k(const float* __restrict__ kv, const float* __restrict__ kva,
                             uint32_t* __restrict__ oh, uint32_t* __restrict__ ol)
{
    int i = blockIdx.x * blockDim.x + threadIdx.x;
    if (i >= ROWS * NHH * 96) return;
    int p = i % 96;
    int r = i / 96;
    int bs = r / NHH;
    float2 v;
    if (p < 64) v = *(const float2*)(kv + (size_t)r * 256 + 2 * p);
    else        v = *(const float2*)(kva + (size_t)bs * KVAW + KVLORA + 2 * (p - 64));
    uint32_t hi, lo; split2b(v.x, v.y, hi, lo);
    oh[i] = hi; ol[i] = lo;
}

// V transpose -> bf16 split [b,h,vd][s/2]
__global__ __launch_bounds__(256) void assemble_v_k(const float* __restrict__ kv,
                             uint32_t* __restrict__ oh, uint32_t* __restrict__ ol)
{
    extern __shared__ float sm[];   // [128][129]
    int sc = blockIdx.x, h = blockIdx.y, b = blockIdx.z;
    int tid = threadIdx.x;
    for (int f = tid; f < 128 * 32; f += 256) {
        int r = f >> 5, c4 = f & 31;
        float4 v = *(const float4*)(kv + ((size_t)((b * SS + sc * 128 + r) * NHH + h)) * 256 + 128 + c4 * 4);
        sm[r * 129 + c4 * 4 + 0] = v.x;
        sm[r * 129 + c4 * 4 + 1] = v.y;
        sm[r * 129 + c4 * 4 + 2] = v.z;
        sm[r * 129 + c4 * 4 + 3] = v.w;
    }
    __syncthreads();
    for (int w = tid; w < 128 * 64; w += 256) {
        int vd = w >> 6, kp = w & 63;
        float a = sm[(2 * kp) * 129 + vd];
        float c = sm[(2 * kp + 1) * 129 + vd];
        uint32_t hi, lo; split2b(a, c, hi, lo);
        size_t oidx = ((size_t)((b * NHH + h) * VHDD + vd)) * (SS / 2) + sc * 64 + kp;
        oh[oidx] = hi; ol[oidx] = lo;
    }
}

// ============================================================================
// HMMA GEMM (fp16 2-pass): C = A @ W^T + bias.
// A pre-split fp16 hi/lo; W plain fp16. CTA 128x128, 8 warps (2x4), K-chunk 32,
// double-buffered. Stage = Ah|Al|Bh = 3*2560 words. 2 CTAs/SM.
// ============================================================================
#define ASZW   2560
#define STAGEW (3*ASZW)
#define GEMM_SMEM (2*STAGEW*4)

__global__ __launch_bounds__(256, 2) void gemm_hmma(
    const uint32_t* __restrict__ Ah_, const uint32_t* __restrict__ Al_, int ldaw,
    const uint32_t* __restrict__ Bh_,
    const float* __restrict__ bias,
    float* __restrict__ C, int N, int K)
{
    extern __shared__ uint32_t smw[];
    const int tid  = threadIdx.x;
    const int lane = tid & 31;
    const int wid  = tid >> 5;
    const int warp_m = wid & 1;
    const int warp_n = wid >> 1;
    const int bm = blockIdx.y * 128;
    const int bn = blockIdx.x * 128;
    const int t = lane & 3;
    const int g = lane >> 2;
    const int ldbw = K >> 1;
    const int nc = K >> 5;

    const int lr = tid >> 2;
    const int lq = tid & 3;
    const bool bv0 = (bn + lr) < N;
    const bool bv1 = (bn + lr + 64) < N;

    float acc[4][4][4];
#pragma unroll
    for (int i = 0; i < 4; i++)
#pragma unroll
        for (int j = 0; j < 4; j++)
#pragma unroll
            for (int k = 0; k < 4; k++) acc[i][j][k] = 0.f;

    uint4 pah[2], pal[2], pbh[2];
    const uint4 z4 = make_uint4(0, 0, 0, 0);

#pragma unroll
    for (int i = 0; i < 2; ++i) {
        int row = lr + i * 64;
        pah[i] = *(const uint4*)(Ah_ + (size_t)(bm + row) * ldaw + lq * 4);
        pal[i] = *(const uint4*)(Al_ + (size_t)(bm + row) * ldaw + lq * 4);
        bool bv = i ? bv1 : bv0;
        pbh[i] = bv ? *(const uint4*)(Bh_ + (size_t)(bn + row) * ldbw + lq * 4) : z4;
    }
    {
        uint32_t* st = smw;
#pragma unroll
        for (int i = 0; i < 2; ++i) {
            int row = lr + i * 64;
            int widx = row * 20 + lq * 4;
            *(uint4*)(st + widx)            = pah[i];
            *(uint4*)(st + ASZW + widx)     = pal[i];
            *(uint4*)(st + 2 * ASZW + widx) = pbh[i];
        }
    }
    __syncthreads();

    for (int ck = 0; ck < nc; ++ck) {
        if (ck + 1 < nc) {
            const int k0w = (ck + 1) << 4;
#pragma unroll
            for (int i = 0; i < 2; ++i) {
                int row = lr + i * 64;
                pah[i] = *(const uint4*)(Ah_ + (size_t)(bm + row) * ldaw + k0w + lq * 4);
                pal[i] = *(const uint4*)(Al_ + (size_t)(bm + row) * ldaw + k0w + lq * 4);
                bool bv = i ? bv1 : bv0;
                pbh[i] = bv ? *(const uint4*)(Bh_ + (size_t)(bn + row) * ldbw + k0w + lq * 4) : z4;
            }
        }
        {
            uint32_t* Ah = smw + (ck & 1) * STAGEW;
            uint32_t* Al = Ah + ASZW;
            uint32_t* Bh = Ah + 2 * ASZW;
#pragma unroll
            for (int k16 = 0; k16 < 2; ++k16) {
                const int kp = k16 * 8;
                uint32_t bh[4][2];
#pragma unroll
                for (int nt = 0; nt < 4; ++nt) {
                    int idx = (warp_n * 32 + nt * 8 + g) * 20 + kp + t;
                    bh[nt][0] = Bh[idx]; bh[nt][1] = Bh[idx + 4];
                }
#pragma unroll
                for (int mt = 0; mt < 4; ++mt) {
                    int base = (warp_m * 64 + mt * 16 + g) * 20 + kp + t;
                    uint32_t ah[4], al[4];
                    ah[0] = Ah[base];     ah[1] = Ah[base + 160];
                    ah[2] = Ah[base + 4]; ah[3] = Ah[base + 164];
                    al[0] = Al[base];     al[1] = Al[base + 160];
                    al[2] = Al[base + 4]; al[3] = Al[base + 164];
#pragma unroll
                    for (int nt = 0; nt < 4; ++nt) {
                        mma_h(acc[mt][nt], ah, bh[nt]);
                        mma_h(acc[mt][nt], al, bh[nt]);
                    }
                }
            }
        }
        if (ck + 1 < nc) {
            uint32_t* st = smw + ((ck + 1) & 1) * STAGEW;
#pragma unroll
            for (int i = 0; i < 2; ++i) {
                int row = lr + i * 64;
                int widx = row * 20 + lq * 4;
                *(uint4*)(st + widx)            = pah[i];
                *(uint4*)(st + ASZW + widx)     = pal[i];
                *(uint4*)(st + 2 * ASZW + widx) = pbh[i];
            }
        }
        __syncthreads();
    }

#pragma unroll
    for (int mt = 0; mt < 4; ++mt) {
        int r0 = bm + warp_m * 64 + mt * 16 + g;
#pragma unroll
        for (int nt = 0; nt < 4; ++nt) {
            int c = bn + warp_n * 32 + nt * 8 + t * 2;
            if (c < N) {
                float2 bv = *(const float2*)(bias + c);
                *(float2*)(C + (size_t)r0 * N + c)       = make_float2(acc[mt][nt][0] + bv.x, acc[mt][nt][1] + bv.y);
                *(float2*)(C + (size_t)(r0 + 8) * N + c) = make_float2(acc[mt][nt][2] + bv.x, acc[mt][nt][3] + bv.y);
            }
        }
    }
}

// ============================================================================
// HMMA flash attention (causal), bf16 3-pass (unchanged layout from R7).
// Epilogue now writes fp16 hi/lo pair-words for the output GEMM.
// ============================================================================
#define FL_QS   0
#define FL_QSL  6400
#define FL_KS   12800
#define FL_KSL  19200
#define FL_VS   25600
#define FL_VSL  30208
#define FL_PS   34816
#define FL_PSL  37120
#define FL_RM   39424
#define FL_RL   39552
#define FL_WORDS 39680
#define FLASH_SMEM (FL_WORDS*4)

__global__ __launch_bounds__(256, 1) void flash_hmma(
    const uint32_t* __restrict__ qh_, const uint32_t* __restrict__ ql_,
    const uint32_t* __restrict__ kh_, const uint32_t* __restrict__ kl_,
    const uint32_t* __restrict__ vh_, const uint32_t* __restrict__ vl_,
    uint32_t* __restrict__ aoh, uint32_t* __restrict__ aol)
{
    extern __shared__ uint32_t sw[];
    float* redm = (float*)(sw + FL_RM);
    float* redl = (float*)(sw + FL_RL);
    const int tid = threadIdx.x;
    const int lane = tid & 31;
    const int wid = tid >> 5;
    const int wm = wid & 3, wn = wid >> 2;
    const int g = lane >> 2, t = lane & 3;
    const int qt = (int)(gridDim.x - 1) - (int)blockIdx.x;
    const int h = blockIdx.y, b = blockIdx.z;
    const int q0 = qt * 64;
    const int row0 = wm * 16 + g, row1 = row0 + 8;

    {
        int r = tid >> 2, qq = tid & 3;
        size_t gb = ((size_t)((b * SS + q0 + r) * NHH + h)) * 96 + qq * 24;
#pragma unroll
        for (int j = 0; j < 6; ++j) {
            *(uint4*)(sw + FL_QS  + r * 100 + qq * 24 + j * 4) = *(const uint4*)(qh_ + gb + j * 4);
            *(uint4*)(sw + FL_QSL + r * 100 + qq * 24 + j * 4) = *(const uint4*)(ql_ + gb + j * 4);
        }
    }

    float o[8][4];
#pragma unroll
    for (int i = 0; i < 8; i++)
#pragma unroll
        for (int j = 0; j < 4; j++) o[i][j] = 0.f;
    float mold0 = -1e30f, mold1 = -1e30f, ls0 = 0.f, ls1 = 0.f;

    for (int kt = 0; kt <= qt; ++kt) {
        const int k0 = kt * 64;
        __syncthreads();
        {
            int r = tid >> 2, qq = tid & 3;
            size_t gb = ((size_t)((b * SS + k0 + r) * NHH + h)) * 96 + qq * 24;
#pragma unroll
            for (int j = 0; j < 6; ++j) {
                *(uint4*)(sw + FL_KS  + r * 100 + qq * 24 + j * 4) = *(const uint4*)(kh_ + gb + j * 4);
                *(uint4*)(sw + FL_KSL + r * 100 + qq * 24 + j * 4) = *(const uint4*)(kl_ + gb + j * 4);
            }
            int vd = tid >> 1, pt = tid & 1;
            size_t vb = ((size_t)((b * NHH + h) * VHDD + vd)) * (SS / 2) + kt * 32 + pt * 16;
#pragma unroll
            for (int j = 0; j < 4; ++j) {
                *(uint4*)(sw + FL_VS  + vd * 36 + pt * 16 + j * 4) = *(const uint4*)(vh_ + vb + j * 4);
                *(uint4*)(sw + FL_VSL + vd * 36 + pt * 16 + j * 4) = *(const uint4*)(vl_ + vb + j * 4);
            }
        }
        __syncthreads();

        float sacc[4][4];
#pragma unroll
        for (int i = 0; i < 4; i++)
#pragma unroll
            for (int j = 0; j < 4; j++) sacc[i][j] = 0.f;
#pragma unroll
        for (int ks = 0; ks < 12; ++ks) {
            int aq = (wm * 16 + g) * 100 + ks * 8 + t;
            uint32_t ah[4], al[4];
            ah[0] = sw[FL_QS + aq];       ah[1] = sw[FL_QS + aq + 800];
            ah[2] = sw[FL_QS + aq + 4];   ah[3] = sw[FL_QS + aq + 804];
            al[0] = sw[FL_QSL + aq];      al[1] = sw[FL_QSL + aq + 800];
            al[2] = sw[FL_QSL + aq + 4];  al[3] = sw[FL_QSL + aq + 804];
#pragma unroll
            for (int nt = 0; nt < 4; ++nt) {
                int bi = (wn * 32 + nt * 8 + g) * 100 + ks * 8 + t;
                uint32_t bh[2] = { sw[FL_KS + bi],  sw[FL_KS + bi + 4] };
                uint32_t bl[2] = { sw[FL_KSL + bi], sw[FL_KSL + bi + 4] };
                mma_bf(sacc[nt], ah, bh);
                mma_bf(sacc[nt], ah, bl);
                mma_bf(sacc[nt], al, bh);
            }
        }

        const bool diag = (kt == qt);
#pragma unroll
        for (int nt = 0; nt < 4; ++nt) {
            sacc[nt][0] *= SCALE_V; sacc[nt][1] *= SCALE_V;
            sacc[nt][2] *= SCALE_V; sacc[nt][3] *= SCALE_V;
            if (diag) {
                int c0 = wn * 32 + nt * 8 + 2 * t;
                if (c0 > row0)     sacc[nt][0] = -1e30f;
                if (c0 + 1 > row0) sacc[nt][1] = -1e30f;
                if (c0 > row1)     sacc[nt][2] = -1e30f;
                if (c0 + 1 > row1) sacc[nt][3] = -1e30f;
            }
        }

        float m0 = -1e30f, m1 = -1e30f;
#pragma unroll
        for (int nt = 0; nt < 4; ++nt) {
            m0 = fmaxf(m0, fmaxf(sacc[nt][0], sacc[nt][1]));
            m1 = fmaxf(m1, fmaxf(sacc[nt][2], sacc[nt][3]));
        }
        m0 = fmaxf(m0, __shfl_xor_sync(0xffffffffu, m0, 1));
        m0 = fmaxf(m0, __shfl_xor_sync(0xffffffffu, m0, 2));
        m1 = fmaxf(m1, __shfl_xor_sync(0xffffffffu, m1, 1));
        m1 = fmaxf(m1, __shfl_xor_sync(0xffffffffu, m1, 2));
        if (t == 0) { redm[wn * 64 + row0] = m0; redm[wn * 64 + row1] = m1; }
        __syncthreads();

        float mnew0 = fmaxf(mold0, fmaxf(redm[row0], redm[64 + row0]));
        float mnew1 = fmaxf(mold1, fmaxf(redm[row1], redm[64 + row1]));
        float fac0 = __expf(mold0 - mnew0);
        float fac1 = __expf(mold1 - mnew1);
        mold0 = mnew0; mold1 = mnew1;

        float sum0 = 0.f, sum1 = 0.f;
#pragma unroll
        for (int nt = 0; nt < 4; ++nt) {
            float p0 = __expf(sacc[nt][0] - mnew0);
            float p1 = __expf(sacc[nt][1] - mnew0);
            float p2 = __expf(sacc[nt][2] - mnew1);
            float p3 = __expf(sacc[nt][3] - mnew1);
            sum0 += p0 + p1; sum1 += p2 + p3;
            uint32_t hi, lo;
            split2b(p0, p1, hi, lo);
            sw[FL_PS  + row0 * 36 + wn * 16 + nt * 4 + t] = hi;
            sw[FL_PSL + row0 * 36 + wn * 16 + nt * 4 + t] = lo;
            split2b(p2, p3, hi, lo);
            sw[FL_PS  + row1 * 36 + wn * 16 + nt * 4 + t] = hi;
            sw[FL_PSL + row1 * 36 + wn * 16 + nt * 4 + t] = lo;
        }
        sum0 += __shfl_xor_sync(0xffffffffu, sum0, 1);
        sum0 += __shfl_xor_sync(0xffffffffu, sum0, 2);
        sum1 += __shfl_xor_sync(0xffffffffu, sum1, 1);
        sum1 += __shfl_xor_sync(0xffffffffu, sum1, 2);
        if (t == 0) { redl[wn * 64 + row0] = sum0; redl[wn * 64 + row1] = sum1; }

#pragma unroll
        for (int nt = 0; nt < 8; ++nt) {
            o[nt][0] *= fac0; o[nt][1] *= fac0;
            o[nt][2] *= fac1; o[nt][3] *= fac1;
        }
        __syncthreads();

        ls0 = ls0 * fac0 + redl[row0] + redl[64 + row0];
        ls1 = ls1 * fac1 + redl[row1] + redl[64 + row1];

#pragma unroll
        for (int ks = 0; ks < 4; ++ks) {
            int pb = (wm * 16 + g) * 36 + ks * 8 + t;
            uint32_t ah[4], al[4];
            ah[0] = sw[FL_PS + pb];       ah[1] = sw[FL_PS + pb + 288];
            ah[2] = sw[FL_PS + pb + 4];   ah[3] = sw[FL_PS + pb + 292];
            al[0] = sw[FL_PSL + pb];      al[1] = sw[FL_PSL + pb + 288];
            al[2] = sw[FL_PSL + pb + 4];  al[3] = sw[FL_PSL + pb + 292];
#pragma unroll
            for (int nt = 0; nt < 8; ++nt) {
                int vi = (wn * 64 + nt * 8 + g) * 36 + ks * 8 + t;
                uint32_t bh[2] = { sw[FL_VS + vi],  sw[FL_VS + vi + 4] };
                uint32_t bl[2] = { sw[FL_VSL + vi], sw[FL_VSL + vi + 4] };
                mma_bf(o[nt], ah, bh);
                mma_bf(o[nt], ah, bl);
                mma_bf(o[nt], al, bh);
            }
        }
    }

    // epilogue: normalize, fp16 split for output GEMM
    float inv0 = 1.0f / ls0, inv1 = 1.0f / ls1;
    size_t r0 = (size_t)(b * SS + q0 + row0) * 1024;
    size_t r1 = (size_t)(b * SS + q0 + row1) * 1024;
#pragma unroll
    for (int nt = 0; nt < 8; ++nt) {
        int word = h * 64 + wn * 32 + nt * 4 + t;
        uint32_t hi, lo;
        split2h(o[nt][0] * inv0, o[nt][1] * inv0, hi, lo);
        aoh[r0 + word] = hi; aol[r0 + word] = lo;
        split2h(o[nt][2] * inv1, o[nt][3] * inv1, hi, lo);
        aoh[r1 + word] = hi; aol[r1 + word] = lo;
    }
}

// ============================================================================
// launch
// ============================================================================
extern "C" void kernel_launch(void* const* d_in, const int* in_sizes, int n_in,
                              void* d_out, int out_size)
{
    const float* x         = (const float*)d_in[0];
    const float* fcos      = (const float*)d_in[1];
    const float* fsin      = (const float*)d_in[2];
    const float* wq_a_w    = (const float*)d_in[3];
    const float* wq_a_b    = (const float*)d_in[4];
    const float* q_norm_w  = (const float*)d_in[5];
    const float* wq_b_w    = (const float*)d_in[6];
    const float* wq_b_b    = (const float*)d_in[7];
    const float* wkv_a_w   = (const float*)d_in[8];
    const float* wkv_a_b   = (const float*)d_in[9];
    const float* kv_norm_w = (const float*)d_in[10];
    const float* wkv_b_w   = (const float*)d_in[11];
    const float* wkv_b_b   = (const float*)d_in[12];
    const float* wo_w      = (const float*)d_in[13];
    const float* wo_b      = (const float*)d_in[14];
    float* out = (float*)d_out;

    float *qa, *q, *kva, *kv;
    uint32_t *xh, *xl, *wh, *qah, *qal, *kvah, *kval;
    uint32_t *qbh, *qbl, *kbh, *kbl, *vbh, *vbl, *aoh, *aol;
    cudaGetSymbolAddress((void**)&qa,   g_qa);
    cudaGetSymbolAddress((void**)&q,    g_q);
    cudaGetSymbolAddress((void**)&kva,  g_kva);
    cudaGetSymbolAddress((void**)&kv,   g_kv);
    cudaGetSymbolAddress((void**)&xh,   g_xh);
    cudaGetSymbolAddress((void**)&xl,   g_xl);
    cudaGetSymbolAddress((void**)&wh,   g_wh);
    cudaGetSymbolAddress((void**)&qah,  g_qah);
    cudaGetSymbolAddress((void**)&qal,  g_qal);
    cudaGetSymbolAddress((void**)&kvah, g_kvah);
    cudaGetSymbolAddress((void**)&kval, g_kval);
    cudaGetSymbolAddress((void**)&qbh,  g_qbh);
    cudaGetSymbolAddress((void**)&qbl,  g_qbl);
    cudaGetSymbolAddress((void**)&kbh,  g_kbh);
    cudaGetSymbolAddress((void**)&kbl,  g_kbl);
    cudaGetSymbolAddress((void**)&vbh,  g_vbh);
    cudaGetSymbolAddress((void**)&vbl,  g_vbl);
    cudaGetSymbolAddress((void**)&aoh,  g_aoh);
    cudaGetSymbolAddress((void**)&aol,  g_aol);

    cudaFuncSetAttribute(gemm_hmma,   cudaFuncAttributeMaxDynamicSharedMemorySize, GEMM_SMEM);
    cudaFuncSetAttribute(flash_hmma,  cudaFuncAttributeMaxDynamicSharedMemorySize, FLASH_SMEM);
    cudaFuncSetAttribute(assemble_v_k, cudaFuncAttributeMaxDynamicSharedMemorySize, 128 * 129 * 4);

    #define CVTA(src, dh, dl, n) cvt_split_h_k<<<((n)/4 + 255)/256, 256>>>(src, dh, dl, (n)/4)
    #define CVTW(src, dh, n)     cvt_h_k<<<((n)/4 + 255)/256, 256>>>(src, dh, (n)/4)

    CVTA(x, xh, xl, ROWS * DIMD);
    // gemm1: qa = x @ wq_a^T + b
    CVTW(wq_a_w, wh, QLORA * DIMD);
    gemm_hmma<<<dim3(QLORA/128, ROWS/128), 256, GEMM_SMEM>>>(xh, xl, DIMD/2, wh, wq_a_b, qa, QLORA, DIMD);
    // gemm2: kva = x @ wkv_a^T + b
    CVTW(wkv_a_w, wh, KVAW * DIMD);
    gemm_hmma<<<dim3((KVAW+127)/128, ROWS/128), 256, GEMM_SMEM>>>(xh, xl, DIMD/2, wh, wkv_a_b, kva, KVAW, DIMD);
    // rmsnorm + fp16 split
    rmsnorm_split_k<<<ROWS, 256>>>(qa, q_norm_w, QLORA, QLORA, qah, qal);
    rmsnorm_split_k<<<ROWS, 256>>>(kva, kv_norm_w, KVAW, KVLORA, kvah, kval);
    // rope k_pe (fp32 in place)
    rope_kpe_k<<<(BB*SS*32)/256, 256>>>(kva, fcos, fsin);
    // gemm3: q = qa_n @ wq_b^T + b
    CVTW(wq_b_w, wh, NHH*QKHD*QLORA);
    gemm_hmma<<<dim3((NHH*QKHD)/128, ROWS/128), 256, GEMM_SMEM>>>(qah, qal, QLORA/2, wh, wq_b_b, q, NHH*QKHD, QLORA);
    // rope + bf16 split q
    cvt_q_rope_k<<<(ROWS*NHH*96 + 255)/256, 256>>>(q, fcos, fsin, qbh, qbl);
    // gemm4: kv = kva_n @ wkv_b^T + b
    CVTW(wkv_b_w, wh, NHH*(NOPED+VHDD)*KVLORA);
    gemm_hmma<<<dim3((NHH*(NOPED+VHDD))/128, ROWS/128), 256, GEMM_SMEM>>>(kvah, kval, KVLORA/2, wh, wkv_b_b, kv, NHH*(NOPED+VHDD), KVLORA);
    // K assembly + V transpose (bf16)
    assemble_k_k<<<(ROWS*NHH*96 + 255)/256, 256>>>(kv, kva, kbh, kbl);
    assemble_v_k<<<dim3(SS/128, NHH, BB), 256, 128*129*4>>>(kv, vbh, vbl);
    // flash attention -> ao (fp16 hi/lo)
    flash_hmma<<<dim3(SS/64, NHH, BB), 256, FLASH_SMEM>>>(qbh, qbl, kbh, kbl, vbh, vbl, aoh, aol);
    // gemm5: out = ao @ wo^T + b
    CVTW(wo_w, wh, DIMD * NHH*VHDD);
    gemm_hmma<<<dim3(DIMD/128, ROWS/128), 256, GEMM_SMEM>>>(aoh, aol, (NHH*VHDD)/2, wh, wo_b, out, DIMD, DIMD);
}

// round 9
// speedup vs baseline: 3.4624x; 1.2413x over previous
#include <cuda_runtime.h>
#include <cuda_bf16.h>
#include <cuda_fp16.h>
#include <cstdint>
#include <math.h>

// ---------------- problem constants ----------------
#define BB      2
#define SS      2048
#define DIMD    2048
#define NHH     16
#define QLORA   1536
#define KVLORA  512
#define ROPED   64
#define NOPED   128
#define VHDD    128
#define QKHD    192
#define KVAW    576
#define ROWS    (BB*SS)
#define SCALE_V 0.07216878364870323f

// ---------------- scratch (device globals) ----------------
__device__ float g_qa [ROWS * QLORA];
__device__ float g_q  [ROWS * (NHH*QKHD)];
__device__ float g_kva[ROWS * KVAW];
__device__ float g_kv [ROWS * (NHH*(NOPED+VHDD))];
// fp16 pair-words for GEMM operands
__device__ uint32_t g_xh  [ROWS * 1024];
__device__ uint32_t g_xl  [ROWS * 1024];
__device__ uint32_t g_wh  [2359296];
__device__ uint32_t g_qah [ROWS * 768];
__device__ uint32_t g_qal [ROWS * 768];
__device__ uint32_t g_kvah[ROWS * 256];
__device__ uint32_t g_kval[ROWS * 256];
__device__ uint32_t g_aoh [ROWS * 1024];
__device__ uint32_t g_aol [ROWS * 1024];
// fp16 pair-words for flash attention (single precision operands)
__device__ uint32_t g_qb  [ROWS * NHH * 96];
__device__ uint32_t g_kb  [ROWS * NHH * 96];
__device__ uint32_t g_vb  [BB * NHH * VHDD * (SS/2)];

// ============================================================================
// helpers
// ============================================================================
__device__ __forceinline__ uint32_t pack_h(float a, float b) {
    uint16_t lo16 = __half_as_ushort(__float2half_rn(a));
    uint16_t hi16 = __half_as_ushort(__float2half_rn(b));
    return (uint32_t)lo16 | ((uint32_t)hi16 << 16);
}
__device__ __forceinline__ void split2h(float a, float b, uint32_t& hi, uint32_t& lo) {
    float ha = __half2float(__float2half_rn(a));
    float hb = __half2float(__float2half_rn(b));
    hi = pack_h(a, b);
    lo = pack_h(a - ha, b - hb);
}
__device__ __forceinline__ void cvt_split4h(float4 v, uint2& hi, uint2& lo) {
    split2h(v.x, v.y, hi.x, lo.x);
    split2h(v.z, v.w, hi.y, lo.y);
}
__device__ __forceinline__ void mma_h(float* d, const uint32_t* a, const uint32_t* b) {
    asm volatile(
        "mma.sync.aligned.m16n8k16.row.col.f32.f16.f16.f32 "
        "{%0,%1,%2,%3}, {%4,%5,%6,%7}, {%8,%9}, {%0,%1,%2,%3};"
        : "+f"(d[0]), "+f"(d[1]), "+f"(d[2]), "+f"(d[3])
        : "r"(a[0]), "r"(a[1]), "r"(a[2]), "r"(a[3]), "r"(b[0]), "r"(b[1]));
}

// ============================================================================
// conversion / prep kernels
// ============================================================================
__global__ void cvt_split_h_k(const float* __restrict__ in,
                              uint32_t* __restrict__ oh, uint32_t* __restrict__ ol, int n4)
{
    int i = blockIdx.x * blockDim.x + threadIdx.x;
    if (i < n4) {
        float4 v = *(const float4*)(in + 4 * (size_t)i);
        uint2 hi, lo; cvt_split4h(v, hi, lo);
        *(uint2*)(oh + 2 * (size_t)i) = hi;
        *(uint2*)(ol + 2 * (size_t)i) = lo;
    }
}
__global__ void cvt_h_k(const float* __restrict__ in, uint32_t* __restrict__ oh, int n4)
{
    int i = blockIdx.x * blockDim.x + threadIdx.x;
    if (i < n4) {
        float4 v = *(const float4*)(in + 4 * (size_t)i);
        uint2 hi;
        hi.x = pack_h(v.x, v.y);
        hi.y = pack_h(v.z, v.w);
        *(uint2*)(oh + 2 * (size_t)i) = hi;
    }
}

__global__ __launch_bounds__(256) void rmsnorm_split_k(
    const float* __restrict__ x, const float* __restrict__ w, int stride, int n,
    uint32_t* __restrict__ oh, uint32_t* __restrict__ ol)
{
    const float* row = x + (size_t)blockIdx.x * stride;
    float ss = 0.f;
    for (int i = threadIdx.x * 4; i < n; i += 1024) {
        float4 v = *(const float4*)(row + i);
        ss += v.x * v.x + v.y * v.y + v.z * v.z + v.w * v.w;
    }
#pragma unroll
    for (int off = 16; off; off >>= 1) ss += __shfl_xor_sync(0xffffffffu, ss, off);
    __shared__ float ws[8];
    if ((threadIdx.x & 31) == 0) ws[threadIdx.x >> 5] = ss;
    __syncthreads();
    float tot = 0.f;
#pragma unroll
    for (int i = 0; i < 8; i++) tot += ws[i];
    float r = rsqrtf(tot / (float)n + 1e-6f);
    const int ow = n >> 1;
    for (int i = threadIdx.x * 4; i < n; i += 1024) {
        float4 v  = *(const float4*)(row + i);
        float4 wv = *(const float4*)(w + i);
        v.x *= r * wv.x; v.y *= r * wv.y; v.z *= r * wv.z; v.w *= r * wv.w;
        uint2 hi, lo; cvt_split4h(v, hi, lo);
        *(uint2*)(oh + (size_t)blockIdx.x * ow + (i >> 1)) = hi;
        *(uint2*)(ol + (size_t)blockIdx.x * ow + (i >> 1)) = lo;
    }
}

__global__ void rope_kpe_k(float* __restrict__ kva,
                           const float* __restrict__ cosd, const float* __restrict__ sind)
{
    int idx = blockIdx.x * blockDim.x + threadIdx.x;
    int i = idx & 31;
    int s = (idx >> 5) & 2047;
    int b = idx >> 16;
    float* p = kva + (size_t)(b * SS + s) * KVAW + KVLORA + 2 * i;
    float c = cosd[s * 32 + i], sn = sind[s * 32 + i];
    float xr = p[0], xi = p[1];
    p[0] = xr * c - xi * sn;
    p[1] = xr * sn + xi * c;
}

// q fp32 -> roped + fp16 pair-words
__global__ void cvt_q_rope_k(const float* __restrict__ q,
                             const float* __restrict__ cosd, const float* __restrict__ sind,
                             uint32_t* __restrict__ o)
{
    int i = blockIdx.x * blockDim.x + threadIdx.x;
    if (i >= ROWS * NHH * 96) return;
    int p = i % 96;
    int s = (i / (96 * NHH)) % SS;
    float2 v = *(const float2*)(q + 2 * (size_t)i);
    if (p >= 64) {
        int ri = p - 64;
        float c = cosd[s * 32 + ri], sn = sind[s * 32 + ri];
        float xr = v.x, xi = v.y;
        v.x = xr * c - xi * sn;
        v.y = xr * sn + xi * c;
    }
    o[i] = pack_h(v.x, v.y);
}

// K = concat(kv[...,0:128], kpe) -> fp16 pair-words [b,s,h][96]
__global__ void assemble_k_k(const float* __restrict__ kv, const float* __restrict__ kva,
                             uint32_t* __restrict__ o)
{
    int i = blockIdx.x * blockDim.x + threadIdx.x;
    if (i >= ROWS * NHH * 96) return;
    int p = i % 96;
    int r = i / 96;
    int bs = r / NHH;
    float2 v;
    if (p < 64) v = *(const float2*)(kv + (size_t)r * 256 + 2 * p);
    else        v = *(const float2*)(kva + (size_t)bs * KVAW + KVLORA + 2 * (p - 64));
    o[i] = pack_h(v.x, v.y);
}

// V transpose -> fp16 pair-words [b,h,vd][s/2]
__global__ __launch_bounds__(256) void assemble_v_k(const float* __restrict__ kv,
                             uint32_t* __restrict__ o)
{
    extern __shared__ float sm[];   // [128][129]
    int sc = blockIdx.x, h = blockIdx.y, b = blockIdx.z;
    int tid = threadIdx.x;
    for (int f = tid; f < 128 * 32; f += 256) {
        int r = f >> 5, c4 = f & 31;
        float4 v = *(const float4*)(kv + ((size_t)((b * SS + sc * 128 + r) * NHH + h)) * 256 + 128 + c4 * 4);
        sm[r * 129 + c4 * 4 + 0] = v.x;
        sm[r * 129 + c4 * 4 + 1] = v.y;
        sm[r * 129 + c4 * 4 + 2] = v.z;
        sm[r * 129 + c4 * 4 + 3] = v.w;
    }
    __syncthreads();
    for (int w = tid; w < 128 * 64; w += 256) {
        int vd = w >> 6, kp = w & 63;
        float a = sm[(2 * kp) * 129 + vd];
        float c = sm[(2 * kp + 1) * 129 + vd];
        size_t oidx = ((size_t)((b * NHH + h) * VHDD + vd)) * (SS / 2) + sc * 64 + kp;
        o[oidx] = pack_h(a, c);
    }
}

// ============================================================================
// HMMA GEMM (fp16 2-pass) — unchanged from R8
// ============================================================================
#define ASZW   2560
#define STAGEW (3*ASZW)
#define GEMM_SMEM (2*STAGEW*4)

__global__ __launch_bounds__(256, 2) void gemm_hmma(
    const uint32_t* __restrict__ Ah_, const uint32_t* __restrict__ Al_, int ldaw,
    const uint32_t* __restrict__ Bh_,
    const float* __restrict__ bias,
    float* __restrict__ C, int N, int K)
{
    extern __shared__ uint32_t smw[];
    const int tid  = threadIdx.x;
    const int lane = tid & 31;
    const int wid  = tid >> 5;
    const int warp_m = wid & 1;
    const int warp_n = wid >> 1;
    const int bm = blockIdx.y * 128;
    const int bn = blockIdx.x * 128;
    const int t = lane & 3;
    const int g = lane >> 2;
    const int ldbw = K >> 1;
    const int nc = K >> 5;

    const int lr = tid >> 2;
    const int lq = tid & 3;
    const bool bv0 = (bn + lr) < N;
    const bool bv1 = (bn + lr + 64) < N;

    float acc[4][4][4];
#pragma unroll
    for (int i = 0; i < 4; i++)
#pragma unroll
        for (int j = 0; j < 4; j++)
#pragma unroll
            for (int k = 0; k < 4; k++) acc[i][j][k] = 0.f;

    uint4 pah[2], pal[2], pbh[2];
    const uint4 z4 = make_uint4(0, 0, 0, 0);

#pragma unroll
    for (int i = 0; i < 2; ++i) {
        int row = lr + i * 64;
        pah[i] = *(const uint4*)(Ah_ + (size_t)(bm + row) * ldaw + lq * 4);
        pal[i] = *(const uint4*)(Al_ + (size_t)(bm + row) * ldaw + lq * 4);
        bool bv = i ? bv1 : bv0;
        pbh[i] = bv ? *(const uint4*)(Bh_ + (size_t)(bn + row) * ldbw + lq * 4) : z4;
    }
    {
        uint32_t* st = smw;
#pragma unroll
        for (int i = 0; i < 2; ++i) {
            int row = lr + i * 64;
            int widx = row * 20 + lq * 4;
            *(uint4*)(st + widx)            = pah[i];
            *(uint4*)(st + ASZW + widx)     = pal[i];
            *(uint4*)(st + 2 * ASZW + widx) = pbh[i];
        }
    }
    __syncthreads();

    for (int ck = 0; ck < nc; ++ck) {
        if (ck + 1 < nc) {
            const int k0w = (ck + 1) << 4;
#pragma unroll
            for (int i = 0; i < 2; ++i) {
                int row = lr + i * 64;
                pah[i] = *(const uint4*)(Ah_ + (size_t)(bm + row) * ldaw + k0w + lq * 4);
                pal[i] = *(const uint4*)(Al_ + (size_t)(bm + row) * ldaw + k0w + lq * 4);
                bool bv = i ? bv1 : bv0;
                pbh[i] = bv ? *(const uint4*)(Bh_ + (size_t)(bn + row) * ldbw + k0w + lq * 4) : z4;
            }
        }
        {
            uint32_t* Ah = smw + (ck & 1) * STAGEW;
            uint32_t* Al = Ah + ASZW;
            uint32_t* Bh = Ah + 2 * ASZW;
#pragma unroll
            for (int k16 = 0; k16 < 2; ++k16) {
                const int kp = k16 * 8;
                uint32_t bh[4][2];
#pragma unroll
                for (int nt = 0; nt < 4; ++nt) {
                    int idx = (warp_n * 32 + nt * 8 + g) * 20 + kp + t;
                    bh[nt][0] = Bh[idx]; bh[nt][1] = Bh[idx + 4];
                }
#pragma unroll
                for (int mt = 0; mt < 4; ++mt) {
                    int base = (warp_m * 64 + mt * 16 + g) * 20 + kp + t;
                    uint32_t ah[4], al[4];
                    ah[0] = Ah[base];     ah[1] = Ah[base + 160];
                    ah[2] = Ah[base + 4]; ah[3] = Ah[base + 164];
                    al[0] = Al[base];     al[1] = Al[base + 160];
                    al[2] = Al[base + 4]; al[3] = Al[base + 164];
#pragma unroll
                    for (int nt = 0; nt < 4; ++nt) {
                        mma_h(acc[mt][nt], ah, bh[nt]);
                        mma_h(acc[mt][nt], al, bh[nt]);
                    }
                }
            }
        }
        if (ck + 1 < nc) {
            uint32_t* st = smw + ((ck + 1) & 1) * STAGEW;
#pragma unroll
            for (int i = 0; i < 2; ++i) {
                int row = lr + i * 64;
                int widx = row * 20 + lq * 4;
                *(uint4*)(st + widx)            = pah[i];
                *(uint4*)(st + ASZW + widx)     = pal[i];
                *(uint4*)(st + 2 * ASZW + widx) = pbh[i];
            }
        }
        __syncthreads();
    }

#pragma unroll
    for (int mt = 0; mt < 4; ++mt) {
        int r0 = bm + warp_m * 64 + mt * 16 + g;
#pragma unroll
        for (int nt = 0; nt < 4; ++nt) {
            int c = bn + warp_n * 32 + nt * 8 + t * 2;
            if (c < N) {
                float2 bv = *(const float2*)(bias + c);
                *(float2*)(C + (size_t)r0 * N + c)       = make_float2(acc[mt][nt][0] + bv.x, acc[mt][nt][1] + bv.y);
                *(float2*)(C + (size_t)(r0 + 8) * N + c) = make_float2(acc[mt][nt][2] + bv.x, acc[mt][nt][3] + bv.y);
            }
        }
    }
}

// ============================================================================
// HMMA flash attention (causal), 1-pass fp16. 2 CTAs/SM.
// ============================================================================
#define FL_QS   0
#define FL_KS   6400
#define FL_VS   12800
#define FL_PS   17408
#define FL_RM   19712
#define FL_RL   19840
#define FL_WORDS 19968
#define FLASH_SMEM (FL_WORDS*4)

__global__ __launch_bounds__(256, 2) void flash_hmma(
    const uint32_t* __restrict__ qh_,
    const uint32_t* __restrict__ kh_,
    const uint32_t* __restrict__ vh_,
    uint32_t* __restrict__ aoh, uint32_t* __restrict__ aol)
{
    extern __shared__ uint32_t sw[];
    float* redm = (float*)(sw + FL_RM);
    float* redl = (float*)(sw + FL_RL);
    const int tid = threadIdx.x;
    const int lane = tid & 31;
    const int wid = tid >> 5;
    const int wm = wid & 3, wn = wid >> 2;
    const int g = lane >> 2, t = lane & 3;
    const int qt = (int)(gridDim.x - 1) - (int)blockIdx.x;
    const int h = blockIdx.y, b = blockIdx.z;
    const int q0 = qt * 64;
    const int row0 = wm * 16 + g, row1 = row0 + 8;

    // load Q tile (once)
    {
        int r = tid >> 2, qq = tid & 3;
        size_t gb = ((size_t)((b * SS + q0 + r) * NHH + h)) * 96 + qq * 24;
#pragma unroll
        for (int j = 0; j < 6; ++j)
            *(uint4*)(sw + FL_QS + r * 100 + qq * 24 + j * 4) = *(const uint4*)(qh_ + gb + j * 4);
    }

    float o[8][4];
#pragma unroll
    for (int i = 0; i < 8; i++)
#pragma unroll
        for (int j = 0; j < 4; j++) o[i][j] = 0.f;
    float mold0 = -1e30f, mold1 = -1e30f, ls0 = 0.f, ls1 = 0.f;

    for (int kt = 0; kt <= qt; ++kt) {
        const int k0 = kt * 64;
        __syncthreads();   // prev PV done
        {
            int r = tid >> 2, qq = tid & 3;
            size_t gb = ((size_t)((b * SS + k0 + r) * NHH + h)) * 96 + qq * 24;
#pragma unroll
            for (int j = 0; j < 6; ++j)
                *(uint4*)(sw + FL_KS + r * 100 + qq * 24 + j * 4) = *(const uint4*)(kh_ + gb + j * 4);
            int vd = tid >> 1, pt = tid & 1;
            size_t vb = ((size_t)((b * NHH + h) * VHDD + vd)) * (SS / 2) + kt * 32 + pt * 16;
#pragma unroll
            for (int j = 0; j < 4; ++j)
                *(uint4*)(sw + FL_VS + vd * 36 + pt * 16 + j * 4) = *(const uint4*)(vh_ + vb + j * 4);
        }
        __syncthreads();

        // scores: S[64x64], warp tile 16x32, 1-pass fp16
        float sacc[4][4];
#pragma unroll
        for (int i = 0; i < 4; i++)
#pragma unroll
            for (int j = 0; j < 4; j++) sacc[i][j] = 0.f;
#pragma unroll
        for (int ks = 0; ks < 12; ++ks) {
            int aq = (wm * 16 + g) * 100 + ks * 8 + t;
            uint32_t ah[4];
            ah[0] = sw[FL_QS + aq];       ah[1] = sw[FL_QS + aq + 800];
            ah[2] = sw[FL_QS + aq + 4];   ah[3] = sw[FL_QS + aq + 804];
#pragma unroll
            for (int nt = 0; nt < 4; ++nt) {
                int bi = (wn * 32 + nt * 8 + g) * 100 + ks * 8 + t;
                uint32_t bh[2] = { sw[FL_KS + bi], sw[FL_KS + bi + 4] };
                mma_h(sacc[nt], ah, bh);
            }
        }

        const bool diag = (kt == qt);
#pragma unroll
        for (int nt = 0; nt < 4; ++nt) {
            sacc[nt][0] *= SCALE_V; sacc[nt][1] *= SCALE_V;
            sacc[nt][2] *= SCALE_V; sacc[nt][3] *= SCALE_V;
            if (diag) {
                int c0 = wn * 32 + nt * 8 + 2 * t;
                if (c0 > row0)     sacc[nt][0] = -1e30f;
                if (c0 + 1 > row0) sacc[nt][1] = -1e30f;
                if (c0 > row1)     sacc[nt][2] = -1e30f;
                if (c0 + 1 > row1) sacc[nt][3] = -1e30f;
            }
        }

        float m0 = -1e30f, m1 = -1e30f;
#pragma unroll
        for (int nt = 0; nt < 4; ++nt) {
            m0 = fmaxf(m0, fmaxf(sacc[nt][0], sacc[nt][1]));
            m1 = fmaxf(m1, fmaxf(sacc[nt][2], sacc[nt][3]));
        }
        m0 = fmaxf(m0, __shfl_xor_sync(0xffffffffu, m0, 1));
        m0 = fmaxf(m0, __shfl_xor_sync(0xffffffffu, m0, 2));
        m1 = fmaxf(m1, __shfl_xor_sync(0xffffffffu, m1, 1));
        m1 = fmaxf(m1, __shfl_xor_sync(0xffffffffu, m1, 2));
        if (t == 0) { redm[wn * 64 + row0] = m0; redm[wn * 64 + row1] = m1; }
        __syncthreads();

        float mnew0 = fmaxf(mold0, fmaxf(redm[row0], redm[64 + row0]));
        float mnew1 = fmaxf(mold1, fmaxf(redm[row1], redm[64 + row1]));
        float fac0 = __expf(mold0 - mnew0);
        float fac1 = __expf(mold1 - mnew1);
        mold0 = mnew0; mold1 = mnew1;

        float sum0 = 0.f, sum1 = 0.f;
#pragma unroll
        for (int nt = 0; nt < 4; ++nt) {
            float p0 = __expf(sacc[nt][0] - mnew0);
            float p1 = __expf(sacc[nt][1] - mnew0);
            float p2 = __expf(sacc[nt][2] - mnew1);
            float p3 = __expf(sacc[nt][3] - mnew1);
            sum0 += p0 + p1; sum1 += p2 + p3;
            sw[FL_PS + row0 * 36 + wn * 16 + nt * 4 + t] = pack_h(p0, p1);
            sw[FL_PS + row1 * 36 + wn * 16 + nt * 4 + t] = pack_h(p2, p3);
        }
        sum0 += __shfl_xor_sync(0xffffffffu, sum0, 1);
        sum0 += __shfl_xor_sync(0xffffffffu, sum0, 2);
        sum1 += __shfl_xor_sync(0xffffffffu, sum1, 1);
        sum1 += __shfl_xor_sync(0xffffffffu, sum1, 2);
        if (t == 0) { redl[wn * 64 + row0] = sum0; redl[wn * 64 + row1] = sum1; }

#pragma unroll
        for (int nt = 0; nt < 8; ++nt) {
            o[nt][0] *= fac0; o[nt][1] *= fac0;
            o[nt][2] *= fac1; o[nt][3] *= fac1;
        }
        __syncthreads();

        ls0 = ls0 * fac0 + redl[row0] + redl[64 + row0];
        ls1 = ls1 * fac1 + redl[row1] + redl[64 + row1];

        // PV: O[64x128] += P @ V; warp tile 16x64, 1-pass fp16
#pragma unroll
        for (int ks = 0; ks < 4; ++ks) {
            int pb = (wm * 16 + g) * 36 + ks * 8 + t;
            uint32_t ah[4];
            ah[0] = sw[FL_PS + pb];       ah[1] = sw[FL_PS + pb + 288];
            ah[2] = sw[FL_PS + pb + 4];   ah[3] = sw[FL_PS + pb + 292];
#pragma unroll
            for (int nt = 0; nt < 8; ++nt) {
                int vi = (wn * 64 + nt * 8 + g) * 36 + ks * 8 + t;
                uint32_t bh[2] = { sw[FL_VS + vi], sw[FL_VS + vi + 4] };
                mma_h(o[nt], ah, bh);
            }
        }
    }

    // epilogue: normalize, fp16 hi/lo split for output GEMM
    float inv0 = 1.0f / ls0, inv1 = 1.0f / ls1;
    size_t r0 = (size_t)(b * SS + q0 + row0) * 1024;
    size_t r1 = (size_t)(b * SS + q0 + row1) * 1024;
#pragma unroll
    for (int nt = 0; nt < 8; ++nt) {
        int word = h * 64 + wn * 32 + nt * 4 + t;
        uint32_t hi, lo;
        split2h(o[nt][0] * inv0, o[nt][1] * inv0, hi, lo);
        aoh[r0 + word] = hi; aol[r0 + word] = lo;
        split2h(o[nt][2] * inv1, o[nt][3] * inv1, hi, lo);
        aoh[r1 + word] = hi; aol[r1 + word] = lo;
    }
}

// ============================================================================
// launch
// ============================================================================
extern "C" void kernel_launch(void* const* d_in, const int* in_sizes, int n_in,
                              void* d_out, int out_size)
{
    const float* x         = (const float*)d_in[0];
    const float* fcos      = (const float*)d_in[1];
    const float* fsin      = (const float*)d_in[2];
    const float* wq_a_w    = (const float*)d_in[3];
    const float* wq_a_b    = (const float*)d_in[4];
    const float* q_norm_w  = (const float*)d_in[5];
    const float* wq_b_w    = (const float*)d_in[6];
    const float* wq_b_b    = (const float*)d_in[7];
    const float* wkv_a_w   = (const float*)d_in[8];
    const float* wkv_a_b   = (const float*)d_in[9];
    const float* kv_norm_w = (const float*)d_in[10];
    const float* wkv_b_w   = (const float*)d_in[11];
    const float* wkv_b_b   = (const float*)d_in[12];
    const float* wo_w      = (const float*)d_in[13];
    const float* wo_b      = (const float*)d_in[14];
    float* out = (float*)d_out;

    float *qa, *q, *kva, *kv;
    uint32_t *xh, *xl, *wh, *qah, *qal, *kvah, *kval;
    uint32_t *qb, *kb, *vb, *aoh, *aol;
    cudaGetSymbolAddress((void**)&qa,   g_qa);
    cudaGetSymbolAddress((void**)&q,    g_q);
    cudaGetSymbolAddress((void**)&kva,  g_kva);
    cudaGetSymbolAddress((void**)&kv,   g_kv);
    cudaGetSymbolAddress((void**)&xh,   g_xh);
    cudaGetSymbolAddress((void**)&xl,   g_xl);
    cudaGetSymbolAddress((void**)&wh,   g_wh);
    cudaGetSymbolAddress((void**)&qah,  g_qah);
    cudaGetSymbolAddress((void**)&qal,  g_qal);
    cudaGetSymbolAddress((void**)&kvah, g_kvah);
    cudaGetSymbolAddress((void**)&kval, g_kval);
    cudaGetSymbolAddress((void**)&qb,   g_qb);
    cudaGetSymbolAddress((void**)&kb,   g_kb);
    cudaGetSymbolAddress((void**)&vb,   g_vb);
    cudaGetSymbolAddress((void**)&aoh,  g_aoh);
    cudaGetSymbolAddress((void**)&aol,  g_aol);

    cudaFuncSetAttribute(gemm_hmma,   cudaFuncAttributeMaxDynamicSharedMemorySize, GEMM_SMEM);
    cudaFuncSetAttribute(flash_hmma,  cudaFuncAttributeMaxDynamicSharedMemorySize, FLASH_SMEM);
    cudaFuncSetAttribute(assemble_v_k, cudaFuncAttributeMaxDynamicSharedMemorySize, 128 * 129 * 4);

    #define CVTA(src, dh, dl, n) cvt_split_h_k<<<((n)/4 + 255)/256, 256>>>(src, dh, dl, (n)/4)
    #define CVTW(src, dh, n)     cvt_h_k<<<((n)/4 + 255)/256, 256>>>(src, dh, (n)/4)

    CVTA(x, xh, xl, ROWS * DIMD);
    // gemm1: qa = x @ wq_a^T + b
    CVTW(wq_a_w, wh, QLORA * DIMD);
    gemm_hmma<<<dim3(QLORA/128, ROWS/128), 256, GEMM_SMEM>>>(xh, xl, DIMD/2, wh, wq_a_b, qa, QLORA, DIMD);
    // gemm2: kva = x @ wkv_a^T + b
    CVTW(wkv_a_w, wh, KVAW * DIMD);
    gemm_hmma<<<dim3((KVAW+127)/128, ROWS/128), 256, GEMM_SMEM>>>(xh, xl, DIMD/2, wh, wkv_a_b, kva, KVAW, DIMD);
    // rmsnorm + fp16 split
    rmsnorm_split_k<<<ROWS, 256>>>(qa, q_norm_w, QLORA, QLORA, qah, qal);
    rmsnorm_split_k<<<ROWS, 256>>>(kva, kv_norm_w, KVAW, KVLORA, kvah, kval);
    // rope k_pe (fp32 in place)
    rope_kpe_k<<<(BB*SS*32)/256, 256>>>(kva, fcos, fsin);
    // gemm3: q = qa_n @ wq_b^T + b
    CVTW(wq_b_w, wh, NHH*QKHD*QLORA);
    gemm_hmma<<<dim3((NHH*QKHD)/128, ROWS/128), 256, GEMM_SMEM>>>(qah, qal, QLORA/2, wh, wq_b_b, q, NHH*QKHD, QLORA);
    // rope + fp16 q
    cvt_q_rope_k<<<(ROWS*NHH*96 + 255)/256, 256>>>(q, fcos, fsin, qb);
    // gemm4: kv = kva_n @ wkv_b^T + b
    CVTW(wkv_b_w, wh, NHH*(NOPED+VHDD)*KVLORA);
    gemm_hmma<<<dim3((NHH*(NOPED+VHDD))/128, ROWS/128), 256, GEMM_SMEM>>>(kvah, kval, KVLORA/2, wh, wkv_b_b, kv, NHH*(NOPED+VHDD), KVLORA);
    // K assembly + V transpose (fp16)
    assemble_k_k<<<(ROWS*NHH*96 + 255)/256, 256>>>(kv, kva, kb);
    assemble_v_k<<<dim3(SS/128, NHH, BB), 256, 128*129*4>>>(kv, vb);
    // flash attention -> ao (fp16 hi/lo)
    flash_hmma<<<dim3(SS/64, NHH, BB), 256, FLASH_SMEM>>>(qb, kb, vb, aoh, aol);
    // gemm5: out = ao @ wo^T + b
    CVTW(wo_w, wh, DIMD * NHH*VHDD);
    gemm_hmma<<<dim3(DIMD/128, ROWS/128), 256, GEMM_SMEM>>>(aoh, aol, (NHH*VHDD)/2, wh, wo_b, out, DIMD, DIMD);
}

// round 10
// speedup vs baseline: 5.0237x; 1.4509x over previous
#include <cuda_runtime.h>
#include <cuda_fp16.h>
#include <cstdint>
#include <math.h>

// ---------------- problem constants ----------------
#define BB      2
#define SS      2048
#define DIMD    2048
#define NHH     16
#define QLORA   1536
#define KVLORA  512
#define ROPED   64
#define NOPED   128
#define VHDD    128
#define QKHD    192
#define KVAW    576
#define ROWS    (BB*SS)
#define SCALE_V 0.07216878364870323f

// ---------------- scratch (device globals) ----------------
__device__ float g_qa [ROWS * QLORA];
__device__ float g_kva[ROWS * KVAW];
__device__ float g_kv [ROWS * (NHH*(NOPED+VHDD))];
// fp16 pair-words
__device__ uint32_t g_xh  [ROWS * 1024];
__device__ uint32_t g_wh  [2359296];
__device__ uint32_t g_qah [ROWS * 768];
__device__ uint32_t g_kvah[ROWS * 256];
__device__ uint32_t g_aoh [ROWS * 1024];
__device__ uint32_t g_qb  [ROWS * NHH * 96];
__device__ uint32_t g_kb  [ROWS * NHH * 96];
__device__ uint32_t g_vb  [BB * NHH * VHDD * (SS/2)];

// ============================================================================
// helpers
// ============================================================================
__device__ __forceinline__ uint32_t pack_h(float a, float b) {
    uint16_t lo16 = __half_as_ushort(__float2half_rn(a));
    uint16_t hi16 = __half_as_ushort(__float2half_rn(b));
    return (uint32_t)lo16 | ((uint32_t)hi16 << 16);
}
__device__ __forceinline__ void mma_h(float* d, const uint32_t* a, const uint32_t* b) {
    asm volatile(
        "mma.sync.aligned.m16n8k16.row.col.f32.f16.f16.f32 "
        "{%0,%1,%2,%3}, {%4,%5,%6,%7}, {%8,%9}, {%0,%1,%2,%3};"
        : "+f"(d[0]), "+f"(d[1]), "+f"(d[2]), "+f"(d[3])
        : "r"(a[0]), "r"(a[1]), "r"(a[2]), "r"(a[3]), "r"(b[0]), "r"(b[1]));
}

// ============================================================================
// conversion / prep kernels
// ============================================================================
__global__ void cvt_h_k(const float* __restrict__ in, uint32_t* __restrict__ oh, int n4)
{
    int i = blockIdx.x * blockDim.x + threadIdx.x;
    if (i < n4) {
        float4 v = *(const float4*)(in + 4 * (size_t)i);
        uint2 hi;
        hi.x = pack_h(v.x, v.y);
        hi.y = pack_h(v.z, v.w);
        *(uint2*)(oh + 2 * (size_t)i) = hi;
    }
}

__global__ __launch_bounds__(256) void rmsnorm_h_k(
    const float* __restrict__ x, const float* __restrict__ w, int stride, int n,
    uint32_t* __restrict__ oh)
{
    const float* row = x + (size_t)blockIdx.x * stride;
    float ss = 0.f;
    for (int i = threadIdx.x * 4; i < n; i += 1024) {
        float4 v = *(const float4*)(row + i);
        ss += v.x * v.x + v.y * v.y + v.z * v.z + v.w * v.w;
    }
#pragma unroll
    for (int off = 16; off; off >>= 1) ss += __shfl_xor_sync(0xffffffffu, ss, off);
    __shared__ float ws[8];
    if ((threadIdx.x & 31) == 0) ws[threadIdx.x >> 5] = ss;
    __syncthreads();
    float tot = 0.f;
#pragma unroll
    for (int i = 0; i < 8; i++) tot += ws[i];
    float r = rsqrtf(tot / (float)n + 1e-6f);
    const int ow = n >> 1;
    for (int i = threadIdx.x * 4; i < n; i += 1024) {
        float4 v  = *(const float4*)(row + i);
        float4 wv = *(const float4*)(w + i);
        v.x *= r * wv.x; v.y *= r * wv.y; v.z *= r * wv.z; v.w *= r * wv.w;
        uint2 hi;
        hi.x = pack_h(v.x, v.y);
        hi.y = pack_h(v.z, v.w);
        *(uint2*)(oh + (size_t)blockIdx.x * ow + (i >> 1)) = hi;
    }
}

// rope on k_pe in g_kva (fp32, cols 512..575)
__global__ void rope_kpe_k(float* __restrict__ kva,
                           const float* __restrict__ cosd, const float* __restrict__ sind)
{
    int idx = blockIdx.x * blockDim.x + threadIdx.x;
    int i = idx & 31;
    int s = (idx >> 5) & 2047;
    int b = idx >> 16;
    float* p = kva + (size_t)(b * SS + s) * KVAW + KVLORA + 2 * i;
    float c = cosd[s * 32 + i], sn = sind[s * 32 + i];
    float xr = p[0], xi = p[1];
    p[0] = xr * c - xi * sn;
    p[1] = xr * sn + xi * c;
}

// fill kpe part of kb (words 64..95 per (row,h)) from roped kva
__global__ void assemble_kpe_k(const float* __restrict__ kva, uint32_t* __restrict__ kb)
{
    int i = blockIdx.x * blockDim.x + threadIdx.x;
    if (i >= ROWS * NHH * 32) return;
    int wp = i & 31;
    int hh = (i >> 5) & 15;
    int bs = i >> 9;
    float2 v = *(const float2*)(kva + (size_t)bs * KVAW + KVLORA + 2 * wp);
    kb[(size_t)bs * 1536 + hh * 96 + 64 + wp] = pack_h(v.x, v.y);
}

// V transpose -> fp16 pair-words [b,h,vd][s/2]
__global__ __launch_bounds__(256) void assemble_v_k(const float* __restrict__ kv,
                             uint32_t* __restrict__ o)
{
    extern __shared__ float sm[];   // [128][129]
    int sc = blockIdx.x, h = blockIdx.y, b = blockIdx.z;
    int tid = threadIdx.x;
    for (int f = tid; f < 128 * 32; f += 256) {
        int r = f >> 5, c4 = f & 31;
        float4 v = *(const float4*)(kv + ((size_t)((b * SS + sc * 128 + r) * NHH + h)) * 256 + 128 + c4 * 4);
        sm[r * 129 + c4 * 4 + 0] = v.x;
        sm[r * 129 + c4 * 4 + 1] = v.y;
        sm[r * 129 + c4 * 4 + 2] = v.z;
        sm[r * 129 + c4 * 4 + 3] = v.w;
    }
    __syncthreads();
    for (int w = tid; w < 128 * 64; w += 256) {
        int vd = w >> 6, kp = w & 63;
        float a = sm[(2 * kp) * 129 + vd];
        float c = sm[(2 * kp + 1) * 129 + vd];
        size_t oidx = ((size_t)((b * NHH + h) * VHDD + vd)) * (SS / 2) + sc * 64 + kp;
        o[oidx] = pack_h(a, c);
    }
}

// ============================================================================
// HMMA GEMM (fp16 1-pass): C = A @ W^T + bias. A, W plain fp16 pair-words.
// CTA 128x128, 8 warps (2x4), K-chunk 32, double-buffered. Stage = Ah|Bh.
// Epilogue modes:
//   0: write C fp32
//   1: q path — apply RoPE to d>=128 (per-head d = c%192), pack fp16 to qout
//   2: kv path — write C fp32 AND pack nope cols (c%256<128) fp16 to qout
// ============================================================================
#define ASZW   2560
#define STAGEW (2*ASZW)
#define GEMM_SMEM (2*STAGEW*4)

__global__ __launch_bounds__(256, 2) void gemm_hmma(
    const uint32_t* __restrict__ Ah_, int ldaw,
    const uint32_t* __restrict__ Bh_,
    const float* __restrict__ bias,
    float* __restrict__ C, int N, int K,
    int mode,
    const float* __restrict__ cosd, const float* __restrict__ sind,
    uint32_t* __restrict__ qout)
{
    extern __shared__ uint32_t smw[];
    const int tid  = threadIdx.x;
    const int lane = tid & 31;
    const int wid  = tid >> 5;
    const int warp_m = wid & 1;
    const int warp_n = wid >> 1;
    const int bm = blockIdx.y * 128;
    const int bn = blockIdx.x * 128;
    const int t = lane & 3;
    const int g = lane >> 2;
    const int ldbw = K >> 1;
    const int nc = K >> 5;

    const int lr = tid >> 2;
    const int lq = tid & 3;
    const bool bv0 = (bn + lr) < N;
    const bool bv1 = (bn + lr + 64) < N;

    float acc[4][4][4];
#pragma unroll
    for (int i = 0; i < 4; i++)
#pragma unroll
        for (int j = 0; j < 4; j++)
#pragma unroll
            for (int k = 0; k < 4; k++) acc[i][j][k] = 0.f;

    uint4 pah[2], pbh[2];
    const uint4 z4 = make_uint4(0, 0, 0, 0);

#pragma unroll
    for (int i = 0; i < 2; ++i) {
        int row = lr + i * 64;
        pah[i] = *(const uint4*)(Ah_ + (size_t)(bm + row) * ldaw + lq * 4);
        bool bv = i ? bv1 : bv0;
        pbh[i] = bv ? *(const uint4*)(Bh_ + (size_t)(bn + row) * ldbw + lq * 4) : z4;
    }
    {
        uint32_t* st = smw;
#pragma unroll
        for (int i = 0; i < 2; ++i) {
            int row = lr + i * 64;
            int widx = row * 20 + lq * 4;
            *(uint4*)(st + widx)        = pah[i];
            *(uint4*)(st + ASZW + widx) = pbh[i];
        }
    }
    __syncthreads();

    for (int ck = 0; ck < nc; ++ck) {
        if (ck + 1 < nc) {
            const int k0w = (ck + 1) << 4;
#pragma unroll
            for (int i = 0; i < 2; ++i) {
                int row = lr + i * 64;
                pah[i] = *(const uint4*)(Ah_ + (size_t)(bm + row) * ldaw + k0w + lq * 4);
                bool bv = i ? bv1 : bv0;
                pbh[i] = bv ? *(const uint4*)(Bh_ + (size_t)(bn + row) * ldbw + k0w + lq * 4) : z4;
            }
        }
        {
            uint32_t* Ah = smw + (ck & 1) * STAGEW;
            uint32_t* Bh = Ah + ASZW;
#pragma unroll
            for (int k16 = 0; k16 < 2; ++k16) {
                const int kp = k16 * 8;
                uint32_t bh[4][2];
#pragma unroll
                for (int nt = 0; nt < 4; ++nt) {
                    int idx = (warp_n * 32 + nt * 8 + g) * 20 + kp + t;
                    bh[nt][0] = Bh[idx]; bh[nt][1] = Bh[idx + 4];
                }
#pragma unroll
                for (int mt = 0; mt < 4; ++mt) {
                    int base = (warp_m * 64 + mt * 16 + g) * 20 + kp + t;
                    uint32_t ah[4];
                    ah[0] = Ah[base];     ah[1] = Ah[base + 160];
                    ah[2] = Ah[base + 4]; ah[3] = Ah[base + 164];
#pragma unroll
                    for (int nt = 0; nt < 4; ++nt)
                        mma_h(acc[mt][nt], ah, bh[nt]);
                }
            }
        }
        if (ck + 1 < nc) {
            uint32_t* st = smw + ((ck + 1) & 1) * STAGEW;
#pragma unroll
            for (int i = 0; i < 2; ++i) {
                int row = lr + i * 64;
                int widx = row * 20 + lq * 4;
                *(uint4*)(st + widx)        = pah[i];
                *(uint4*)(st + ASZW + widx) = pbh[i];
            }
        }
        __syncthreads();
    }

#pragma unroll
    for (int mt = 0; mt < 4; ++mt) {
        int r0 = bm + warp_m * 64 + mt * 16 + g;
        int r1 = r0 + 8;
#pragma unroll
        for (int nt = 0; nt < 4; ++nt) {
            int c = bn + warp_n * 32 + nt * 8 + t * 2;
            if (c >= N) continue;
            float2 bv = *(const float2*)(bias + c);
            float a0 = acc[mt][nt][0] + bv.x, a1 = acc[mt][nt][1] + bv.y;
            float a2 = acc[mt][nt][2] + bv.x, a3 = acc[mt][nt][3] + bv.y;
            if (mode == 0) {
                *(float2*)(C + (size_t)r0 * N + c) = make_float2(a0, a1);
                *(float2*)(C + (size_t)r1 * N + c) = make_float2(a2, a3);
            } else if (mode == 1) {
                int d = c % 192;
                if (d >= 128) {
                    int ri = (d - 128) >> 1;
                    int s0 = r0 & (SS - 1), s1 = r1 & (SS - 1);
                    float c0 = cosd[s0 * 32 + ri], n0 = sind[s0 * 32 + ri];
                    float c1 = cosd[s1 * 32 + ri], n1 = sind[s1 * 32 + ri];
                    float x0 = a0, y0 = a1, x1 = a2, y1 = a3;
                    a0 = x0 * c0 - y0 * n0;  a1 = x0 * n0 + y0 * c0;
                    a2 = x1 * c1 - y1 * n1;  a3 = x1 * n1 + y1 * c1;
                }
                qout[(size_t)r0 * 1536 + (c >> 1)] = pack_h(a0, a1);
                qout[(size_t)r1 * 1536 + (c >> 1)] = pack_h(a2, a3);
            } else { // mode 2
                *(float2*)(C + (size_t)r0 * N + c) = make_float2(a0, a1);
                *(float2*)(C + (size_t)r1 * N + c) = make_float2(a2, a3);
                int blk = c & 255;
                if (blk < 128) {
                    int hh = c >> 8;
                    qout[(size_t)r0 * 1536 + hh * 96 + (blk >> 1)] = pack_h(a0, a1);
                    qout[(size_t)r1 * 1536 + hh * 96 + (blk >> 1)] = pack_h(a2, a3);
                }
            }
        }
    }
}

// ============================================================================
// HMMA flash attention (causal), 1-pass fp16. 2 CTAs/SM. (R9 layout)
// ============================================================================
#define FL_QS   0
#define FL_KS   6400
#define FL_VS   12800
#define FL_PS   17408
#define FL_RM   19712
#define FL_RL   19840
#define FL_WORDS 19968
#define FLASH_SMEM (FL_WORDS*4)

__global__ __launch_bounds__(256, 2) void flash_hmma(
    const uint32_t* __restrict__ qh_,
    const uint32_t* __restrict__ kh_,
    const uint32_t* __restrict__ vh_,
    uint32_t* __restrict__ aoh)
{
    extern __shared__ uint32_t sw[];
    float* redm = (float*)(sw + FL_RM);
    float* redl = (float*)(sw + FL_RL);
    const int tid = threadIdx.x;
    const int lane = tid & 31;
    const int wid = tid >> 5;
    const int wm = wid & 3, wn = wid >> 2;
    const int g = lane >> 2, t = lane & 3;
    const int qt = (int)(gridDim.x - 1) - (int)blockIdx.x;
    const int h = blockIdx.y, b = blockIdx.z;
    const int q0 = qt * 64;
    const int row0 = wm * 16 + g, row1 = row0 + 8;

    {
        int r = tid >> 2, qq = tid & 3;
        size_t gb = ((size_t)((b * SS + q0 + r) * NHH + h)) * 96 + qq * 24;
#pragma unroll
        for (int j = 0; j < 6; ++j)
            *(uint4*)(sw + FL_QS + r * 100 + qq * 24 + j * 4) = *(const uint4*)(qh_ + gb + j * 4);
    }

    float o[8][4];
#pragma unroll
    for (int i = 0; i < 8; i++)
#pragma unroll
        for (int j = 0; j < 4; j++) o[i][j] = 0.f;
    float mold0 = -1e30f, mold1 = -1e30f, ls0 = 0.f, ls1 = 0.f;

    for (int kt = 0; kt <= qt; ++kt) {
        const int k0 = kt * 64;
        __syncthreads();
        {
            int r = tid >> 2, qq = tid & 3;
            size_t gb = ((size_t)((b * SS + k0 + r) * NHH + h)) * 96 + qq * 24;
#pragma unroll
            for (int j = 0; j < 6; ++j)
                *(uint4*)(sw + FL_KS + r * 100 + qq * 24 + j * 4) = *(const uint4*)(kh_ + gb + j * 4);
            int vd = tid >> 1, pt = tid & 1;
            size_t vb = ((size_t)((b * NHH + h) * VHDD + vd)) * (SS / 2) + kt * 32 + pt * 16;
#pragma unroll
            for (int j = 0; j < 4; ++j)
                *(uint4*)(sw + FL_VS + vd * 36 + pt * 16 + j * 4) = *(const uint4*)(vh_ + vb + j * 4);
        }
        __syncthreads();

        float sacc[4][4];
#pragma unroll
        for (int i = 0; i < 4; i++)
#pragma unroll
            for (int j = 0; j < 4; j++) sacc[i][j] = 0.f;
#pragma unroll
        for (int ks = 0; ks < 12; ++ks) {
            int aq = (wm * 16 + g) * 100 + ks * 8 + t;
            uint32_t ah[4];
            ah[0] = sw[FL_QS + aq];       ah[1] = sw[FL_QS + aq + 800];
            ah[2] = sw[FL_QS + aq + 4];   ah[3] = sw[FL_QS + aq + 804];
#pragma unroll
            for (int nt = 0; nt < 4; ++nt) {
                int bi = (wn * 32 + nt * 8 + g) * 100 + ks * 8 + t;
                uint32_t bh[2] = { sw[FL_KS + bi], sw[FL_KS + bi + 4] };
                mma_h(sacc[nt], ah, bh);
            }
        }

        const bool diag = (kt == qt);
#pragma unroll
        for (int nt = 0; nt < 4; ++nt) {
            sacc[nt][0] *= SCALE_V; sacc[nt][1] *= SCALE_V;
            sacc[nt][2] *= SCALE_V; sacc[nt][3] *= SCALE_V;
            if (diag) {
                int c0 = wn * 32 + nt * 8 + 2 * t;
                if (c0 > row0)     sacc[nt][0] = -1e30f;
                if (c0 + 1 > row0) sacc[nt][1] = -1e30f;
                if (c0 > row1)     sacc[nt][2] = -1e30f;
                if (c0 + 1 > row1) sacc[nt][3] = -1e30f;
            }
        }

        float m0 = -1e30f, m1 = -1e30f;
#pragma unroll
        for (int nt = 0; nt < 4; ++nt) {
            m0 = fmaxf(m0, fmaxf(sacc[nt][0], sacc[nt][1]));
            m1 = fmaxf(m1, fmaxf(sacc[nt][2], sacc[nt][3]));
        }
        m0 = fmaxf(m0, __shfl_xor_sync(0xffffffffu, m0, 1));
        m0 = fmaxf(m0, __shfl_xor_sync(0xffffffffu, m0, 2));
        m1 = fmaxf(m1, __shfl_xor_sync(0xffffffffu, m1, 1));
        m1 = fmaxf(m1, __shfl_xor_sync(0xffffffffu, m1, 2));
        if (t == 0) { redm[wn * 64 + row0] = m0; redm[wn * 64 + row1] = m1; }
        __syncthreads();

        float mnew0 = fmaxf(mold0, fmaxf(redm[row0], redm[64 + row0]));
        float mnew1 = fmaxf(mold1, fmaxf(redm[row1], redm[64 + row1]));
        float fac0 = __expf(mold0 - mnew0);
        float fac1 = __expf(mold1 - mnew1);
        mold0 = mnew0; mold1 = mnew1;

        float sum0 = 0.f, sum1 = 0.f;
#pragma unroll
        for (int nt = 0; nt < 4; ++nt) {
            float p0 = __expf(sacc[nt][0] - mnew0);
            float p1 = __expf(sacc[nt][1] - mnew0);
            float p2 = __expf(sacc[nt][2] - mnew1);
            float p3 = __expf(sacc[nt][3] - mnew1);
            sum0 += p0 + p1; sum1 += p2 + p3;
            sw[FL_PS + row0 * 36 + wn * 16 + nt * 4 + t] = pack_h(p0, p1);
            sw[FL_PS + row1 * 36 + wn * 16 + nt * 4 + t] = pack_h(p2, p3);
        }
        sum0 += __shfl_xor_sync(0xffffffffu, sum0, 1);
        sum0 += __shfl_xor_sync(0xffffffffu, sum0, 2);
        sum1 += __shfl_xor_sync(0xffffffffu, sum1, 1);
        sum1 += __shfl_xor_sync(0xffffffffu, sum1, 2);
        if (t == 0) { redl[wn * 64 + row0] = sum0; redl[wn * 64 + row1] = sum1; }

#pragma unroll
        for (int nt = 0; nt < 8; ++nt) {
            o[nt][0] *= fac0; o[nt][1] *= fac0;
            o[nt][2] *= fac1; o[nt][3] *= fac1;
        }
        __syncthreads();

        ls0 = ls0 * fac0 + redl[row0] + redl[64 + row0];
        ls1 = ls1 * fac1 + redl[row1] + redl[64 + row1];

#pragma unroll
        for (int ks = 0; ks < 4; ++ks) {
            int pb = (wm * 16 + g) * 36 + ks * 8 + t;
            uint32_t ah[4];
            ah[0] = sw[FL_PS + pb];       ah[1] = sw[FL_PS + pb + 288];
            ah[2] = sw[FL_PS + pb + 4];   ah[3] = sw[FL_PS + pb + 292];
#pragma unroll
            for (int nt = 0; nt < 8; ++nt) {
                int vi = (wn * 64 + nt * 8 + g) * 36 + ks * 8 + t;
                uint32_t bh[2] = { sw[FL_VS + vi], sw[FL_VS + vi + 4] };
                mma_h(o[nt], ah, bh);
            }
        }
    }

    float inv0 = 1.0f / ls0, inv1 = 1.0f / ls1;
    size_t r0 = (size_t)(b * SS + q0 + row0) * 1024;
    size_t r1 = (size_t)(b * SS + q0 + row1) * 1024;
#pragma unroll
    for (int nt = 0; nt < 8; ++nt) {
        int word = h * 64 + wn * 32 + nt * 4 + t;
        aoh[r0 + word] = pack_h(o[nt][0] * inv0, o[nt][1] * inv0);
        aoh[r1 + word] = pack_h(o[nt][2] * inv1, o[nt][3] * inv1);
    }
}

// ============================================================================
// launch
// ============================================================================
extern "C" void kernel_launch(void* const* d_in, const int* in_sizes, int n_in,
                              void* d_out, int out_size)
{
    const float* x         = (const float*)d_in[0];
    const float* fcos      = (const float*)d_in[1];
    const float* fsin      = (const float*)d_in[2];
    const float* wq_a_w    = (const float*)d_in[3];
    const float* wq_a_b    = (const float*)d_in[4];
    const float* q_norm_w  = (const float*)d_in[5];
    const float* wq_b_w    = (const float*)d_in[6];
    const float* wq_b_b    = (const float*)d_in[7];
    const float* wkv_a_w   = (const float*)d_in[8];
    const float* wkv_a_b   = (const float*)d_in[9];
    const float* kv_norm_w = (const float*)d_in[10];
    const float* wkv_b_w   = (const float*)d_in[11];
    const float* wkv_b_b   = (const float*)d_in[12];
    const float* wo_w      = (const float*)d_in[13];
    const float* wo_b      = (const float*)d_in[14];
    float* out = (float*)d_out;

    float *qa, *kva, *kv;
    uint32_t *xh, *wh, *qah, *kvah, *qb, *kb, *vb, *aoh;
    cudaGetSymbolAddress((void**)&qa,   g_qa);
    cudaGetSymbolAddress((void**)&kva,  g_kva);
    cudaGetSymbolAddress((void**)&kv,   g_kv);
    cudaGetSymbolAddress((void**)&xh,   g_xh);
    cudaGetSymbolAddress((void**)&wh,   g_wh);
    cudaGetSymbolAddress((void**)&qah,  g_qah);
    cudaGetSymbolAddress((void**)&kvah, g_kvah);
    cudaGetSymbolAddress((void**)&qb,   g_qb);
    cudaGetSymbolAddress((void**)&kb,   g_kb);
    cudaGetSymbolAddress((void**)&vb,   g_vb);
    cudaGetSymbolAddress((void**)&aoh,  g_aoh);

    cudaFuncSetAttribute(gemm_hmma,   cudaFuncAttributeMaxDynamicSharedMemorySize, GEMM_SMEM);
    cudaFuncSetAttribute(flash_hmma,  cudaFuncAttributeMaxDynamicSharedMemorySize, FLASH_SMEM);
    cudaFuncSetAttribute(assemble_v_k, cudaFuncAttributeMaxDynamicSharedMemorySize, 128 * 129 * 4);

    #define CVTW(src, dh, n) cvt_h_k<<<((n)/4 + 255)/256, 256>>>(src, dh, (n)/4)

    CVTW(x, xh, ROWS * DIMD);
    // gemm1: qa = x @ wq_a^T + b  (fp32 out for rmsnorm)
    CVTW(wq_a_w, wh, QLORA * DIMD);
    gemm_hmma<<<dim3(QLORA/128, ROWS/128), 256, GEMM_SMEM>>>(
        xh, DIMD/2, wh, wq_a_b, qa, QLORA, DIMD, 0, nullptr, nullptr, nullptr);
    // gemm2: kva = x @ wkv_a^T + b
    CVTW(wkv_a_w, wh, KVAW * DIMD);
    gemm_hmma<<<dim3((KVAW+127)/128, ROWS/128), 256, GEMM_SMEM>>>(
        xh, DIMD/2, wh, wkv_a_b, kva, KVAW, DIMD, 0, nullptr, nullptr, nullptr);
    // rmsnorm -> fp16
    rmsnorm_h_k<<<ROWS, 256>>>(qa, q_norm_w, QLORA, QLORA, qah);
    rmsnorm_h_k<<<ROWS, 256>>>(kva, kv_norm_w, KVAW, KVLORA, kvah);
    // rope k_pe (fp32 in place)
    rope_kpe_k<<<(BB*SS*32)/256, 256>>>(kva, fcos, fsin);
    // gemm3: q = qa_n @ wq_b^T + b  -> fused rope + fp16 pack into qb
    CVTW(wq_b_w, wh, NHH*QKHD*QLORA);
    gemm_hmma<<<dim3((NHH*QKHD)/128, ROWS/128), 256, GEMM_SMEM>>>(
        qah, QLORA/2, wh, wq_b_b, nullptr, NHH*QKHD, QLORA, 1, fcos, fsin, qb);
    // gemm4: kv = kva_n @ wkv_b^T + b  -> fp32 kv + fused K-nope pack into kb
    CVTW(wkv_b_w, wh, NHH*(NOPED+VHDD)*KVLORA);
    gemm_hmma<<<dim3((NHH*(NOPED+VHDD))/128, ROWS/128), 256, GEMM_SMEM>>>(
        kvah, KVLORA/2, wh, wkv_b_b, kv, NHH*(NOPED+VHDD), KVLORA, 2, nullptr, nullptr, kb);
    // K pe fill + V transpose
    assemble_kpe_k<<<(ROWS*NHH*32)/256, 256>>>(kva, kb);
    assemble_v_k<<<dim3(SS/128, NHH, BB), 256, 128*129*4>>>(kv, vb);
    // flash attention -> aoh (fp16)
    flash_hmma<<<dim3(SS/64, NHH, BB), 256, FLASH_SMEM>>>(qb, kb, vb, aoh);
    // gemm5: out = ao @ wo^T + b
    CVTW(wo_w, wh, DIMD * NHH*VHDD);
    gemm_hmma<<<dim3(DIMD/128, ROWS/128), 256, GEMM_SMEM>>>(
        aoh, (NHH*VHDD)/2, wh, wo_b, out, DIMD, DIMD, 0, nullptr, nullptr, nullptr);
}

// round 11
// speedup vs baseline: 5.1556x; 1.0263x over previous
#include <cuda_runtime.h>
#include <cuda_fp16.h>
#include <cstdint>
#include <math.h>

// ---------------- problem constants ----------------
#define BB      2
#define SS      2048
#define DIMD    2048
#define NHH     16
#define QLORA   1536
#define KVLORA  512
#define ROPED   64
#define NOPED   128
#define VHDD    128
#define QKHD    192
#define KVAW    576
#define ROWS    (BB*SS)
#define SCALE_V 0.07216878364870323f

// ---------------- scratch (device globals) ----------------
__device__ float g_qa [ROWS * QLORA];
__device__ float g_kva[ROWS * KVAW];
// fp16 pair-words
__device__ uint32_t g_xh  [ROWS * 1024];
__device__ uint32_t g_wh  [2359296];
__device__ uint32_t g_qah [ROWS * 768];
__device__ uint32_t g_kvah[ROWS * 256];
__device__ uint32_t g_aoh [ROWS * 1024];
__device__ uint32_t g_qb  [ROWS * NHH * 96];
__device__ uint32_t g_kb  [ROWS * NHH * 96];
__device__ uint32_t g_vb  [BB * NHH * VHDD * (SS/2)];

// ============================================================================
// helpers
// ============================================================================
__device__ __forceinline__ uint32_t pack_h(float a, float b) {
    uint16_t lo16 = __half_as_ushort(__float2half_rn(a));
    uint16_t hi16 = __half_as_ushort(__float2half_rn(b));
    return (uint32_t)lo16 | ((uint32_t)hi16 << 16);
}
__device__ __forceinline__ void mma_h(float* d, const uint32_t* a, const uint32_t* b) {
    asm volatile(
        "mma.sync.aligned.m16n8k16.row.col.f32.f16.f16.f32 "
        "{%0,%1,%2,%3}, {%4,%5,%6,%7}, {%8,%9}, {%0,%1,%2,%3};"
        : "+f"(d[0]), "+f"(d[1]), "+f"(d[2]), "+f"(d[3])
        : "r"(a[0]), "r"(a[1]), "r"(a[2]), "r"(a[3]), "r"(b[0]), "r"(b[1]));
}

// ============================================================================
// conversion / prep kernels
// ============================================================================
// fp32 -> fp16 pair-words, 4 float4 per thread (MLP=4)
__global__ void cvt_h_k(const float* __restrict__ in, uint32_t* __restrict__ oh, int n4)
{
    int i0 = (blockIdx.x * blockDim.x + threadIdx.x) * 4;
    float4 v[4];
#pragma unroll
    for (int j = 0; j < 4; ++j)
        if (i0 + j < n4) v[j] = *(const float4*)(in + 4 * (size_t)(i0 + j));
#pragma unroll
    for (int j = 0; j < 4; ++j)
        if (i0 + j < n4) {
            uint2 hi;
            hi.x = pack_h(v[j].x, v[j].y);
            hi.y = pack_h(v[j].z, v[j].w);
            *(uint2*)(oh + 2 * (size_t)(i0 + j)) = hi;
        }
}

__global__ __launch_bounds__(256) void rmsnorm_h_k(
    const float* __restrict__ x, const float* __restrict__ w, int stride, int n,
    uint32_t* __restrict__ oh)
{
    const float* row = x + (size_t)blockIdx.x * stride;
    float ss = 0.f;
    for (int i = threadIdx.x * 4; i < n; i += 1024) {
        float4 v = *(const float4*)(row + i);
        ss += v.x * v.x + v.y * v.y + v.z * v.z + v.w * v.w;
    }
#pragma unroll
    for (int off = 16; off; off >>= 1) ss += __shfl_xor_sync(0xffffffffu, ss, off);
    __shared__ float ws[8];
    if ((threadIdx.x & 31) == 0) ws[threadIdx.x >> 5] = ss;
    __syncthreads();
    float tot = 0.f;
#pragma unroll
    for (int i = 0; i < 8; i++) tot += ws[i];
    float r = rsqrtf(tot / (float)n + 1e-6f);
    const int ow = n >> 1;
    for (int i = threadIdx.x * 4; i < n; i += 1024) {
        float4 v  = *(const float4*)(row + i);
        float4 wv = *(const float4*)(w + i);
        v.x *= r * wv.x; v.y *= r * wv.y; v.z *= r * wv.z; v.w *= r * wv.w;
        uint2 hi;
        hi.x = pack_h(v.x, v.y);
        hi.y = pack_h(v.z, v.w);
        *(uint2*)(oh + (size_t)blockIdx.x * ow + (i >> 1)) = hi;
    }
}

// rope k_pe from kva and broadcast fp16 pair-words to all 16 heads of kb
__global__ void rope_kpe_bcast_k(const float* __restrict__ kva,
                                 const float* __restrict__ cosd, const float* __restrict__ sind,
                                 uint32_t* __restrict__ kb)
{
    int i = blockIdx.x * blockDim.x + threadIdx.x;   // ROWS*32
    if (i >= ROWS * 32) return;
    int wp = i & 31;
    int bs = i >> 5;
    int s = bs & (SS - 1);
    float2 v = *(const float2*)(kva + (size_t)bs * KVAW + KVLORA + 2 * wp);
    float c = cosd[s * 32 + wp], sn = sind[s * 32 + wp];
    uint32_t w = pack_h(v.x * c - v.y * sn, v.x * sn + v.y * c);
    uint32_t* dst = kb + (size_t)bs * 1536 + 64 + wp;
#pragma unroll
    for (int h = 0; h < 16; ++h) dst[h * 96] = w;
}

// ============================================================================
// HMMA GEMM (fp16 1-pass): CTA 128x128, 8 warps (2x4), K-chunk 32, dbl-buffered.
// Epilogue modes:
//   0: C fp32 + bias
//   1: q path — RoPE on d>=128 (d = c%192), pack fp16 to qout [row][1536]
//   2: dual  — c<QLORA -> C(=qa, ld QLORA)+bias; else -> C2(=kva, ld KVAW)+bias2
//   3: kv fused — nope-half tile packs kb; V-half tile transposes via smem -> vout
// ============================================================================
#define ASZW   2560
#define STAGEW (2*ASZW)
#define GEMM_SMEM (2*STAGEW*4)

__global__ __launch_bounds__(256, 2) void gemm_hmma(
    const uint32_t* __restrict__ Ah_, int ldaw,
    const uint32_t* __restrict__ Bh_,
    const float* __restrict__ bias,
    float* __restrict__ C, int N, int K,
    int mode,
    const float* __restrict__ cosd, const float* __restrict__ sind,
    uint32_t* __restrict__ qout,
    const float* __restrict__ bias2, float* __restrict__ C2,
    uint32_t* __restrict__ vout)
{
    extern __shared__ uint32_t smw[];
    const int tid  = threadIdx.x;
    const int lane = tid & 31;
    const int wid  = tid >> 5;
    const int warp_m = wid & 1;
    const int warp_n = wid >> 1;
    const int bm = blockIdx.y * 128;
    const int bn = blockIdx.x * 128;
    const int t = lane & 3;
    const int g = lane >> 2;
    const int ldbw = K >> 1;
    const int nc = K >> 5;

    const int lr = tid >> 2;
    const int lq = tid & 3;
    const bool bv0 = (bn + lr) < N;
    const bool bv1 = (bn + lr + 64) < N;

    float acc[4][4][4];
#pragma unroll
    for (int i = 0; i < 4; i++)
#pragma unroll
        for (int j = 0; j < 4; j++)
#pragma unroll
            for (int k = 0; k < 4; k++) acc[i][j][k] = 0.f;

    uint4 pah[2], pbh[2];
    const uint4 z4 = make_uint4(0, 0, 0, 0);

#pragma unroll
    for (int i = 0; i < 2; ++i) {
        int row = lr + i * 64;
        pah[i] = *(const uint4*)(Ah_ + (size_t)(bm + row) * ldaw + lq * 4);
        bool bv = i ? bv1 : bv0;
        pbh[i] = bv ? *(const uint4*)(Bh_ + (size_t)(bn + row) * ldbw + lq * 4) : z4;
    }
    {
        uint32_t* st = smw;
#pragma unroll
        for (int i = 0; i < 2; ++i) {
            int row = lr + i * 64;
            int widx = row * 20 + lq * 4;
            *(uint4*)(st + widx)        = pah[i];
            *(uint4*)(st + ASZW + widx) = pbh[i];
        }
    }
    __syncthreads();

    for (int ck = 0; ck < nc; ++ck) {
        if (ck + 1 < nc) {
            const int k0w = (ck + 1) << 4;
#pragma unroll
            for (int i = 0; i < 2; ++i) {
                int row = lr + i * 64;
                pah[i] = *(const uint4*)(Ah_ + (size_t)(bm + row) * ldaw + k0w + lq * 4);
                bool bv = i ? bv1 : bv0;
                pbh[i] = bv ? *(const uint4*)(Bh_ + (size_t)(bn + row) * ldbw + k0w + lq * 4) : z4;
            }
        }
        {
            uint32_t* Ah = smw + (ck & 1) * STAGEW;
            uint32_t* Bh = Ah + ASZW;
#pragma unroll
            for (int k16 = 0; k16 < 2; ++k16) {
                const int kp = k16 * 8;
                uint32_t bh[4][2];
#pragma unroll
                for (int nt = 0; nt < 4; ++nt) {
                    int idx = (warp_n * 32 + nt * 8 + g) * 20 + kp + t;
                    bh[nt][0] = Bh[idx]; bh[nt][1] = Bh[idx + 4];
                }
#pragma unroll
                for (int mt = 0; mt < 4; ++mt) {
                    int base = (warp_m * 64 + mt * 16 + g) * 20 + kp + t;
                    uint32_t ah[4];
                    ah[0] = Ah[base];     ah[1] = Ah[base + 160];
                    ah[2] = Ah[base + 4]; ah[3] = Ah[base + 164];
#pragma unroll
                    for (int nt = 0; nt < 4; ++nt)
                        mma_h(acc[mt][nt], ah, bh[nt]);
                }
            }
        }
        if (ck + 1 < nc) {
            uint32_t* st = smw + ((ck + 1) & 1) * STAGEW;
#pragma unroll
            for (int i = 0; i < 2; ++i) {
                int row = lr + i * 64;
                int widx = row * 20 + lq * 4;
                *(uint4*)(st + widx)        = pah[i];
                *(uint4*)(st + ASZW + widx) = pbh[i];
            }
        }
        __syncthreads();
    }

    const bool vhalf = (mode == 3) && ((bn >> 7) & 1);
    uint16_t* st16 = (uint16_t*)smw;   // reused as [col 128][row 128] fp16

#pragma unroll
    for (int mt = 0; mt < 4; ++mt) {
        int r0 = bm + warp_m * 64 + mt * 16 + g;
        int r1 = r0 + 8;
#pragma unroll
        for (int nt = 0; nt < 4; ++nt) {
            int c = bn + warp_n * 32 + nt * 8 + t * 2;
            if (c >= N) continue;
            float a0 = acc[mt][nt][0], a1 = acc[mt][nt][1];
            float a2 = acc[mt][nt][2], a3 = acc[mt][nt][3];
            if (mode == 0) {
                float2 bv = *(const float2*)(bias + c);
                a0 += bv.x; a1 += bv.y; a2 += bv.x; a3 += bv.y;
                *(float2*)(C + (size_t)r0 * N + c) = make_float2(a0, a1);
                *(float2*)(C + (size_t)r1 * N + c) = make_float2(a2, a3);
            } else if (mode == 1) {
                float2 bv = *(const float2*)(bias + c);
                a0 += bv.x; a1 += bv.y; a2 += bv.x; a3 += bv.y;
                int d = c % 192;
                if (d >= 128) {
                    int ri = (d - 128) >> 1;
                    int s0 = r0 & (SS - 1), s1 = r1 & (SS - 1);
                    float c0 = cosd[s0 * 32 + ri], n0 = sind[s0 * 32 + ri];
                    float c1 = cosd[s1 * 32 + ri], n1 = sind[s1 * 32 + ri];
                    float x0 = a0, y0 = a1, x1 = a2, y1 = a3;
                    a0 = x0 * c0 - y0 * n0;  a1 = x0 * n0 + y0 * c0;
                    a2 = x1 * c1 - y1 * n1;  a3 = x1 * n1 + y1 * c1;
                }
                qout[(size_t)r0 * 1536 + (c >> 1)] = pack_h(a0, a1);
                qout[(size_t)r1 * 1536 + (c >> 1)] = pack_h(a2, a3);
            } else if (mode == 2) {
                if (c < QLORA) {
                    float2 bv = *(const float2*)(bias + c);
                    a0 += bv.x; a1 += bv.y; a2 += bv.x; a3 += bv.y;
                    *(float2*)(C + (size_t)r0 * QLORA + c) = make_float2(a0, a1);
                    *(float2*)(C + (size_t)r1 * QLORA + c) = make_float2(a2, a3);
                } else {
                    int c2 = c - QLORA;
                    float2 bv = *(const float2*)(bias2 + c2);
                    a0 += bv.x; a1 += bv.y; a2 += bv.x; a3 += bv.y;
                    *(float2*)(C2 + (size_t)r0 * KVAW + c2) = make_float2(a0, a1);
                    *(float2*)(C2 + (size_t)r1 * KVAW + c2) = make_float2(a2, a3);
                }
            } else { // mode 3
                float2 bv = *(const float2*)(bias + c);
                a0 += bv.x; a1 += bv.y; a2 += bv.x; a3 += bv.y;
                if (!vhalf) {
                    int hh = c >> 8;
                    int blk = c & 255;   // < 128 (nope half)
                    qout[(size_t)r0 * 1536 + hh * 96 + (blk >> 1)] = pack_h(a0, a1);
                    qout[(size_t)r1 * 1536 + hh * 96 + (blk >> 1)] = pack_h(a2, a3);
                } else {
                    int cl = c & 127;
                    int rl0 = r0 - bm, rl1 = r1 - bm;
                    st16[(cl + 0) * 128 + rl0] = __half_as_ushort(__float2half_rn(a0));
                    st16[(cl + 1) * 128 + rl0] = __half_as_ushort(__float2half_rn(a1));
                    st16[(cl + 0) * 128 + rl1] = __half_as_ushort(__float2half_rn(a2));
                    st16[(cl + 1) * 128 + rl1] = __half_as_ushort(__float2half_rn(a3));
                }
            }
        }
    }

    if (vhalf) {
        __syncthreads();
        int h = bn >> 8;
        int b = bm / SS;
        int s0 = bm & (SS - 1);
        int vd = tid >> 1;
        int jp0 = (tid & 1) * 32;
        size_t base = ((size_t)((b * NHH + h) * VHDD + vd)) * (SS / 2) + (s0 >> 1) + jp0;
#pragma unroll
        for (int j = 0; j < 32; ++j) {
            uint32_t lo = st16[vd * 128 + 2 * (jp0 + j)];
            uint32_t hi = st16[vd * 128 + 2 * (jp0 + j) + 1];
            vout[base + j] = lo | (hi << 16);
        }
    }
}

// ============================================================================
// HMMA flash attention (causal), 1-pass fp16, 2 CTAs/SM (unchanged from R10)
// ============================================================================
#define FL_QS   0
#define FL_KS   6400
#define FL_VS   12800
#define FL_PS   17408
#define FL_RM   19712
#define FL_RL   19840
#define FL_WORDS 19968
#define FLASH_SMEM (FL_WORDS*4)

__global__ __launch_bounds__(256, 2) void flash_hmma(
    const uint32_t* __restrict__ qh_,
    const uint32_t* __restrict__ kh_,
    const uint32_t* __restrict__ vh_,
    uint32_t* __restrict__ aoh)
{
    extern __shared__ uint32_t sw[];
    float* redm = (float*)(sw + FL_RM);
    float* redl = (float*)(sw + FL_RL);
    const int tid = threadIdx.x;
    const int lane = tid & 31;
    const int wid = tid >> 5;
    const int wm = wid & 3, wn = wid >> 2;
    const int g = lane >> 2, t = lane & 3;
    const int qt = (int)(gridDim.x - 1) - (int)blockIdx.x;
    const int h = blockIdx.y, b = blockIdx.z;
    const int q0 = qt * 64;
    const int row0 = wm * 16 + g, row1 = row0 + 8;

    {
        int r = tid >> 2, qq = tid & 3;
        size_t gb = ((size_t)((b * SS + q0 + r) * NHH + h)) * 96 + qq * 24;
#pragma unroll
        for (int j = 0; j < 6; ++j)
            *(uint4*)(sw + FL_QS + r * 100 + qq * 24 + j * 4) = *(const uint4*)(qh_ + gb + j * 4);
    }

    float o[8][4];
#pragma unroll
    for (int i = 0; i < 8; i++)
#pragma unroll
        for (int j = 0; j < 4; j++) o[i][j] = 0.f;
    float mold0 = -1e30f, mold1 = -1e30f, ls0 = 0.f, ls1 = 0.f;

    for (int kt = 0; kt <= qt; ++kt) {
        const int k0 = kt * 64;
        __syncthreads();
        {
            int r = tid >> 2, qq = tid & 3;
            size_t gb = ((size_t)((b * SS + k0 + r) * NHH + h)) * 96 + qq * 24;
#pragma unroll
            for (int j = 0; j < 6; ++j)
                *(uint4*)(sw + FL_KS + r * 100 + qq * 24 + j * 4) = *(const uint4*)(kh_ + gb + j * 4);
            int vd = tid >> 1, pt = tid & 1;
            size_t vb = ((size_t)((b * NHH + h) * VHDD + vd)) * (SS / 2) + kt * 32 + pt * 16;
#pragma unroll
            for (int j = 0; j < 4; ++j)
                *(uint4*)(sw + FL_VS + vd * 36 + pt * 16 + j * 4) = *(const uint4*)(vh_ + vb + j * 4);
        }
        __syncthreads();

        float sacc[4][4];
#pragma unroll
        for (int i = 0; i < 4; i++)
#pragma unroll
            for (int j = 0; j < 4; j++) sacc[i][j] = 0.f;
#pragma unroll
        for (int ks = 0; ks < 12; ++ks) {
            int aq = (wm * 16 + g) * 100 + ks * 8 + t;
            uint32_t ah[4];
            ah[0] = sw[FL_QS + aq];       ah[1] = sw[FL_QS + aq + 800];
            ah[2] = sw[FL_QS + aq + 4];   ah[3] = sw[FL_QS + aq + 804];
#pragma unroll
            for (int nt = 0; nt < 4; ++nt) {
                int bi = (wn * 32 + nt * 8 + g) * 100 + ks * 8 + t;
                uint32_t bh[2] = { sw[FL_KS + bi], sw[FL_KS + bi + 4] };
                mma_h(sacc[nt], ah, bh);
            }
        }

        const bool diag = (kt == qt);
#pragma unroll
        for (int nt = 0; nt < 4; ++nt) {
            sacc[nt][0] *= SCALE_V; sacc[nt][1] *= SCALE_V;
            sacc[nt][2] *= SCALE_V; sacc[nt][3] *= SCALE_V;
            if (diag) {
                int c0 = wn * 32 + nt * 8 + 2 * t;
                if (c0 > row0)     sacc[nt][0] = -1e30f;
                if (c0 + 1 > row0) sacc[nt][1] = -1e30f;
                if (c0 > row1)     sacc[nt][2] = -1e30f;
                if (c0 + 1 > row1) sacc[nt][3] = -1e30f;
            }
        }

        float m0 = -1e30f, m1 = -1e30f;
#pragma unroll
        for (int nt = 0; nt < 4; ++nt) {
            m0 = fmaxf(m0, fmaxf(sacc[nt][0], sacc[nt][1]));
            m1 = fmaxf(m1, fmaxf(sacc[nt][2], sacc[nt][3]));
        }
        m0 = fmaxf(m0, __shfl_xor_sync(0xffffffffu, m0, 1));
        m0 = fmaxf(m0, __shfl_xor_sync(0xffffffffu, m0, 2));
        m1 = fmaxf(m1, __shfl_xor_sync(0xffffffffu, m1, 1));
        m1 = fmaxf(m1, __shfl_xor_sync(0xffffffffu, m1, 2));
        if (t == 0) { redm[wn * 64 + row0] = m0; redm[wn * 64 + row1] = m1; }
        __syncthreads();

        float mnew0 = fmaxf(mold0, fmaxf(redm[row0], redm[64 + row0]));
        float mnew1 = fmaxf(mold1, fmaxf(redm[row1], redm[64 + row1]));
        float fac0 = __expf(mold0 - mnew0);
        float fac1 = __expf(mold1 - mnew1);
        mold0 = mnew0; mold1 = mnew1;

        float sum0 = 0.f, sum1 = 0.f;
#pragma unroll
        for (int nt = 0; nt < 4; ++nt) {
            float p0 = __expf(sacc[nt][0] - mnew0);
            float p1 = __expf(sacc[nt][1] - mnew0);
            float p2 = __expf(sacc[nt][2] - mnew1);
            float p3 = __expf(sacc[nt][3] - mnew1);
            sum0 += p0 + p1; sum1 += p2 + p3;
            sw[FL_PS + row0 * 36 + wn * 16 + nt * 4 + t] = pack_h(p0, p1);
            sw[FL_PS + row1 * 36 + wn * 16 + nt * 4 + t] = pack_h(p2, p3);
        }
        sum0 += __shfl_xor_sync(0xffffffffu, sum0, 1);
        sum0 += __shfl_xor_sync(0xffffffffu, sum0, 2);
        sum1 += __shfl_xor_sync(0xffffffffu, sum1, 1);
        sum1 += __shfl_xor_sync(0xffffffffu, sum1, 2);
        if (t == 0) { redl[wn * 64 + row0] = sum0; redl[wn * 64 + row1] = sum1; }

#pragma unroll
        for (int nt = 0; nt < 8; ++nt) {
            o[nt][0] *= fac0; o[nt][1] *= fac0;
            o[nt][2] *= fac1; o[nt][3] *= fac1;
        }
        __syncthreads();

        ls0 = ls0 * fac0 + redl[row0] + redl[64 + row0];
        ls1 = ls1 * fac1 + redl[row1] + redl[64 + row1];

#pragma unroll
        for (int ks = 0; ks < 4; ++ks) {
            int pb = (wm * 16 + g) * 36 + ks * 8 + t;
            uint32_t ah[4];
            ah[0] = sw[FL_PS + pb];       ah[1] = sw[FL_PS + pb + 288];
            ah[2] = sw[FL_PS + pb + 4];   ah[3] = sw[FL_PS + pb + 292];
#pragma unroll
            for (int nt = 0; nt < 8; ++nt) {
                int vi = (wn * 64 + nt * 8 + g) * 36 + ks * 8 + t;
                uint32_t bh[2] = { sw[FL_VS + vi], sw[FL_VS + vi + 4] };
                mma_h(o[nt], ah, bh);
            }
        }
    }

    float inv0 = 1.0f / ls0, inv1 = 1.0f / ls1;
    size_t r0 = (size_t)(b * SS + q0 + row0) * 1024;
    size_t r1 = (size_t)(b * SS + q0 + row1) * 1024;
#pragma unroll
    for (int nt = 0; nt < 8; ++nt) {
        int word = h * 64 + wn * 32 + nt * 4 + t;
        aoh[r0 + word] = pack_h(o[nt][0] * inv0, o[nt][1] * inv0);
        aoh[r1 + word] = pack_h(o[nt][2] * inv1, o[nt][3] * inv1);
    }
}

// ============================================================================
// launch
// ============================================================================
extern "C" void kernel_launch(void* const* d_in, const int* in_sizes, int n_in,
                              void* d_out, int out_size)
{
    const float* x         = (const float*)d_in[0];
    const float* fcos      = (const float*)d_in[1];
    const float* fsin      = (const float*)d_in[2];
    const float* wq_a_w    = (const float*)d_in[3];
    const float* wq_a_b    = (const float*)d_in[4];
    const float* q_norm_w  = (const float*)d_in[5];
    const float* wq_b_w    = (const float*)d_in[6];
    const float* wq_b_b    = (const float*)d_in[7];
    const float* wkv_a_w   = (const float*)d_in[8];
    const float* wkv_a_b   = (const float*)d_in[9];
    const float* kv_norm_w = (const float*)d_in[10];
    const float* wkv_b_w   = (const float*)d_in[11];
    const float* wkv_b_b   = (const float*)d_in[12];
    const float* wo_w      = (const float*)d_in[13];
    const float* wo_b      = (const float*)d_in[14];
    float* out = (float*)d_out;

    float *qa, *kva;
    uint32_t *xh, *wh, *qah, *kvah, *qb, *kb, *vb, *aoh;
    cudaGetSymbolAddress((void**)&qa,   g_qa);
    cudaGetSymbolAddress((void**)&kva,  g_kva);
    cudaGetSymbolAddress((void**)&xh,   g_xh);
    cudaGetSymbolAddress((void**)&wh,   g_wh);
    cudaGetSymbolAddress((void**)&qah,  g_qah);
    cudaGetSymbolAddress((void**)&kvah, g_kvah);
    cudaGetSymbolAddress((void**)&qb,   g_qb);
    cudaGetSymbolAddress((void**)&kb,   g_kb);
    cudaGetSymbolAddress((void**)&vb,   g_vb);
    cudaGetSymbolAddress((void**)&aoh,  g_aoh);

    cudaFuncSetAttribute(gemm_hmma,  cudaFuncAttributeMaxDynamicSharedMemorySize, GEMM_SMEM);
    cudaFuncSetAttribute(flash_hmma, cudaFuncAttributeMaxDynamicSharedMemorySize, FLASH_SMEM);

    #define CVTW(src, dh, n) cvt_h_k<<<((n)/16 + 255)/256, 256>>>(src, dh, (n)/4)

    // convert x + both LoRA-A weights (concatenated: wq_a rows 0.., wkv_a rows 1536..)
    CVTW(x, xh, ROWS * DIMD);
    CVTW(wq_a_w,  wh,                     QLORA * DIMD);
    CVTW(wkv_a_w, wh + QLORA * (DIMD/2),  KVAW * DIMD);
    // fused gemm1+2: [qa | kva] = x @ [wq_a; wkv_a]^T + biases   (N = 2112)
    gemm_hmma<<<dim3((QLORA + KVAW + 127)/128, ROWS/128), 256, GEMM_SMEM>>>(
        xh, DIMD/2, wh, wq_a_b, qa, QLORA + KVAW, DIMD, 2,
        nullptr, nullptr, nullptr, wkv_a_b, kva, nullptr);
    // rmsnorm -> fp16
    rmsnorm_h_k<<<ROWS, 256>>>(qa, q_norm_w, QLORA, QLORA, qah);
    rmsnorm_h_k<<<ROWS, 256>>>(kva, kv_norm_w, KVAW, KVLORA, kvah);
    // roped k_pe broadcast into kb (all heads)
    rope_kpe_bcast_k<<<(ROWS*32)/256, 256>>>(kva, fcos, fsin, kb);
    // gemm3: q = qa_n @ wq_b^T + b -> fused rope + fp16 pack into qb
    CVTW(wq_b_w, wh, NHH*QKHD*QLORA);
    gemm_hmma<<<dim3((NHH*QKHD)/128, ROWS/128), 256, GEMM_SMEM>>>(
        qah, QLORA/2, wh, wq_b_b, nullptr, NHH*QKHD, QLORA, 1,
        fcos, fsin, qb, nullptr, nullptr, nullptr);
    // gemm4: kv = kva_n @ wkv_b^T + b -> fused kb-nope pack + V-transpose into vb
    CVTW(wkv_b_w, wh, NHH*(NOPED+VHDD)*KVLORA);
    gemm_hmma<<<dim3((NHH*(NOPED+VHDD))/128, ROWS/128), 256, GEMM_SMEM>>>(
        kvah, KVLORA/2, wh, wkv_b_b, nullptr, NHH*(NOPED+VHDD), KVLORA, 3,
        nullptr, nullptr, kb, nullptr, nullptr, vb);
    // flash attention -> aoh (fp16)
    flash_hmma<<<dim3(SS/64, NHH, BB), 256, FLASH_SMEM>>>(qb, kb, vb, aoh);
    // gemm5: out = ao @ wo^T + b
    CVTW(wo_w, wh, DIMD * NHH*VHDD);
    gemm_hmma<<<dim3(DIMD/128, ROWS/128), 256, GEMM_SMEM>>>(
        aoh, (NHH*VHDD)/2, wh, wo_b, out, DIMD, DIMD, 0,
        nullptr, nullptr, nullptr, nullptr, nullptr, nullptr);
}